// round 3
// baseline (speedup 1.0000x reference)
#include <cuda_runtime.h>
#include <cstdint>
#include <cstddef>

// ---------------------------------------------------------------------------
// Scratch (device globals; no allocation allowed anywhere)
// ---------------------------------------------------------------------------
__device__ float g_xn [16777216];   // max 16384 rows x 1024
__device__ float g_U  [67108864];   // 1024*16*4096
__device__ float g_hA [16777216];
__device__ float g_hB [16777216];
__device__ float g_WihT[4194304];   // 1024 x 4096
__device__ float g_bsum[4096];
__device__ float g_h0 [16384];      // LSTM h ping buffer 0
__device__ float g_h1 [16384];      // LSTM h ping buffer 1
__device__ unsigned g_bar_count;
__device__ unsigned g_bar_gen;

#define LN_EPS 1e-5f

__device__ __forceinline__ float sigf(float x) {
    return __fdividef(1.f, 1.f + __expf(-x));
}

// ---------------------------------------------------------------------------
// Block reduction helper (256-thread blocks)
// ---------------------------------------------------------------------------
__device__ __forceinline__ float blockReduceSum(float v, float* shm) {
    int lane = threadIdx.x & 31, wid = threadIdx.x >> 5;
    #pragma unroll
    for (int o = 16; o; o >>= 1) v += __shfl_xor_sync(0xffffffffu, v, o);
    if (lane == 0) shm[wid] = v;
    __syncthreads();
    int nw = (blockDim.x + 31) >> 5;
    float r = (threadIdx.x < nw) ? shm[threadIdx.x] : 0.f;
    if (wid == 0) {
        #pragma unroll
        for (int o = 16; o; o >>= 1) r += __shfl_xor_sync(0xffffffffu, r, o);
        if (lane == 0) shm[0] = r;
    }
    __syncthreads();
    float total = shm[0];
    __syncthreads();
    return total;
}

// ---------------------------------------------------------------------------
// LayerNorm over last dim. Row r = l*Bb + b. srcBMajor: src is (B,L,D).
// dstBMajor: dst written in (B,L,D) order (for final projection).
// ---------------------------------------------------------------------------
__global__ __launch_bounds__(256) void ln_rows(
    const float* __restrict__ src, float* __restrict__ dst,
    const float* __restrict__ g, const float* __restrict__ be,
    int L, int Bb, int D, int srcBMajor, int dstBMajor)
{
    __shared__ float shm[32];
    int r = blockIdx.x;
    int l = r / Bb, b = r % Bb;
    const float* s = src + (srcBMajor ? ((size_t)b * L + l) : (size_t)r) * D;
    float*       d = dst + (dstBMajor ? ((size_t)b * L + l) : (size_t)r) * D;

    float sum = 0.f;
    for (int i = threadIdx.x; i < D; i += 256) sum += s[i];
    float mean = blockReduceSum(sum, shm) / (float)D;

    float vs = 0.f;
    for (int i = threadIdx.x; i < D; i += 256) { float t = s[i] - mean; vs += t * t; }
    float var = blockReduceSum(vs, shm) / (float)D;
    float rstd = rsqrtf(var + LN_EPS);

    for (int i = threadIdx.x; i < D; i += 256)
        d[i] = (s[i] - mean) * rstd * g[i] + be[i];
}

// ---------------------------------------------------------------------------
// SGEMM: C[M,N] = A[M,K] @ B[K,N] (+bias[n]).  M % 128 == 0, K % 8 == 0.
// BM=BN=128, BK=8, 8x8 per thread, 256 threads.
// ---------------------------------------------------------------------------
__global__ __launch_bounds__(256) void sgemm(
    const float* __restrict__ A, const float* __restrict__ B,
    const float* __restrict__ bias, float* __restrict__ C,
    int M, int N, int K)
{
    __shared__ float As[8][128];
    __shared__ float Bs[8][128];
    const int bn  = blockIdx.x * 128;
    const int bm  = blockIdx.y * 128;
    const int tid = threadIdx.x;
    const int tx   = (tid & 15) << 3;
    const int ty   = (tid >> 4) << 3;
    const int arow = tid >> 1;
    const int acol = (tid & 1) << 2;
    const int brow = tid >> 5;
    const int bcol = (tid & 31) << 2;
    const bool nvec = ((N & 3) == 0) && (bn + 128 <= N);

    float acc[8][8];
    #pragma unroll
    for (int i = 0; i < 8; i++)
        #pragma unroll
        for (int j = 0; j < 8; j++) acc[i][j] = 0.f;

    for (int k0 = 0; k0 < K; k0 += 8) {
        float4 av = *(const float4*)(A + (size_t)(bm + arow) * K + k0 + acol);
        As[acol + 0][arow] = av.x;
        As[acol + 1][arow] = av.y;
        As[acol + 2][arow] = av.z;
        As[acol + 3][arow] = av.w;
        if (nvec) {
            *(float4*)&Bs[brow][bcol] =
                *(const float4*)(B + (size_t)(k0 + brow) * N + bn + bcol);
        } else {
            #pragma unroll
            for (int j = 0; j < 4; j++) {
                int n = bn + bcol + j;
                Bs[brow][bcol + j] = (n < N) ? B[(size_t)(k0 + brow) * N + n] : 0.f;
            }
        }
        __syncthreads();
        #pragma unroll
        for (int kk = 0; kk < 8; kk++) {
            float am[8], bv[8];
            *(float4*)(am)     = *(const float4*)&As[kk][ty];
            *(float4*)(am + 4) = *(const float4*)&As[kk][ty + 4];
            *(float4*)(bv)     = *(const float4*)&Bs[kk][tx];
            *(float4*)(bv + 4) = *(const float4*)&Bs[kk][tx + 4];
            #pragma unroll
            for (int i = 0; i < 8; i++)
                #pragma unroll
                for (int j = 0; j < 8; j++) acc[i][j] += am[i] * bv[j];
        }
        __syncthreads();
    }

    #pragma unroll
    for (int i = 0; i < 8; i++) {
        size_t m = (size_t)bm + ty + i;
        #pragma unroll
        for (int j = 0; j < 8; j++) {
            int n = bn + tx + j;
            if (n < N) {
                float v = acc[i][j];
                if (bias) v += bias[n];
                C[m * N + n] = v;
            }
        }
    }
}

// ---------------------------------------------------------------------------
// SRU scan: 16384 independent recurrences (one per (b,h)); coalesced in h.
// ---------------------------------------------------------------------------
__global__ void sru_scan(
    const float* __restrict__ U, const float* __restrict__ res,
    const float* __restrict__ vc, const float* __restrict__ bias,
    float* __restrict__ out, int L, int Bb, int H, int k)
{
    int idx = blockIdx.x * blockDim.x + threadIdx.x;
    if (idx >= Bb * H) return;
    int hh = idx % H, b = idx / H;
    float vf = vc[hh], vr = vc[H + hh];
    float bf = bias[hh], br = bias[H + hh];
    float c = 0.f;

    size_t ustep = (size_t)Bb * k * H;
    size_t ubase = (size_t)b * k * H + hh;
    size_t ostep = (size_t)Bb * H;
    size_t obase = (size_t)b * H + hh;

    const float* u  = U + ubase;
    const float* rp = (k == 3) ? (res + obase) : (U + ubase + 3 * (size_t)H);
    size_t rstep    = (k == 3) ? ostep : ustep;
    float* o = out + obase;

    for (int t = 0; t < L; ++t) {
        float a0 = u[0], a1 = u[H], a2 = u[2 * (size_t)H];
        float rt = rp[0];
        float f = sigf(a1 + vf * c + bf);
        float r = sigf(a2 + vr * c + br);
        c = f * c + (1.f - f) * a0;
        o[0] = r * c + (1.f - r) * rt;
        u += ustep; rp += rstep; o += ostep;
    }
}

// ---------------------------------------------------------------------------
// Time pooling: mean of adjacent timestep pairs.
// ---------------------------------------------------------------------------
__global__ void pool2(const float* __restrict__ in, float* __restrict__ out, int n)
{
    int i = blockIdx.x * blockDim.x + threadIdx.x;
    if (i >= n) return;
    int lp = i >> 14;
    size_t j = (size_t)i + (size_t)lp * 16384;
    out[i] = 0.5f * (in[j] + in[j + 16384]);
}

__global__ void addvec(const float* __restrict__ a, const float* __restrict__ b,
                       float* __restrict__ o, int n)
{
    int i = blockIdx.x * blockDim.x + threadIdx.x;
    if (i < n) o[i] = a[i] + b[i];
}

// Transpose src[R][C] -> dst[C][R]
__global__ void transpose_k(const float* __restrict__ src, float* __restrict__ dst,
                            int R, int C)
{
    __shared__ float tile[32][33];
    int c0 = blockIdx.x * 32, r0 = blockIdx.y * 32;
    int x = threadIdx.x, y = threadIdx.y;
    #pragma unroll
    for (int j = 0; j < 32; j += 8) {
        int r = r0 + y + j, c = c0 + x;
        if (r < R && c < C) tile[y + j][x] = src[(size_t)r * C + c];
    }
    __syncthreads();
    #pragma unroll
    for (int j = 0; j < 32; j += 8) {
        int r = c0 + y + j, c = r0 + x;
        if (r < C && c < R) dst[(size_t)r * R + c] = tile[x][y + j];
    }
}

// ---------------------------------------------------------------------------
// LSTM init: zero h ping buffer 0 and barrier state (runs every replay).
// ---------------------------------------------------------------------------
__global__ void lstm_init(float* h0)
{
    int i = blockIdx.x * blockDim.x + threadIdx.x;
    if (i < 16384) h0[i] = 0.f;
    if (i == 0) { g_bar_count = 0u; g_bar_gen = 0u; }
}

// ---------------------------------------------------------------------------
// Persistent LSTM: one kernel for all 512 steps. 148 CTAs (1/SM, co-resident),
// software grid barrier per step, h double-buffered in global, c in registers.
// Block bid owns hh in [s, s+cnt): blocks 0..135 -> 7 units, 136..147 -> 6.
// Warp w (w < cnt) computes gate rows {hh, 1024+hh, 2048+hh, 3072+hh} for all
// 16 batches (lane b<16 holds batch b's result after shfl-reduce) and does the
// pointwise update itself -> no intra-step inter-block dependency.
// ---------------------------------------------------------------------------
__global__ __launch_bounds__(256) void lstm_persist(
    const float* __restrict__ pre,   // [512][16][4096] (bias already included)
    const float* __restrict__ Whh,   // [4096][1024]
    float* __restrict__ hbuf0, float* __restrict__ hbuf1,
    float* __restrict__ hout)        // [512][16][1024]
{
    extern __shared__ float hs[];    // 16 x 1024 floats = 64 KB
    float4* hs4 = (float4*)hs;
    const int tid = threadIdx.x, bid = blockIdx.x;
    const int warp = tid >> 5, lane = tid & 31;

    int cnt, s;
    if (bid < 136) { cnt = 7; s = bid * 7; }
    else           { cnt = 6; s = 952 + (bid - 136) * 6; }
    const bool active = warp < cnt;
    const int hh = s + (active ? warp : 0);

    const float4* W4[4];
    #pragma unroll
    for (int g = 0; g < 4; g++)
        W4[g] = (const float4*)(Whh + ((size_t)g * 1024 + hh) * 1024);

    float c = 0.f;

    for (int t = 0; t < 512; t++) {
        const float4* hsrc = (const float4*)((t & 1) ? hbuf1 : hbuf0);
        float*        hdst = (t & 1) ? hbuf0 : hbuf1;

        __syncthreads();
        // h from other blocks was written at L2; bypass (stale) L1 with ldcg.
        for (int i = tid; i < 4096; i += 256) hs4[i] = __ldcg(hsrc + i);
        __syncthreads();

        if (active) {
            float acc[4][16];
            #pragma unroll
            for (int g = 0; g < 4; g++)
                #pragma unroll
                for (int b = 0; b < 16; b++) acc[g][b] = 0.f;

            #pragma unroll 1
            for (int i = lane; i < 256; i += 32) {
                float4 wv[4];
                #pragma unroll
                for (int g = 0; g < 4; g++) wv[g] = W4[g][i];
                #pragma unroll
                for (int b = 0; b < 16; b++) {
                    float4 hv = hs4[b * 256 + i];
                    #pragma unroll
                    for (int g = 0; g < 4; g++)
                        acc[g][b] += wv[g].x * hv.x + wv[g].y * hv.y
                                   + wv[g].z * hv.z + wv[g].w * hv.w;
                }
            }

            float gate[4] = {0.f, 0.f, 0.f, 0.f};
            #pragma unroll
            for (int g = 0; g < 4; g++)
                #pragma unroll
                for (int b = 0; b < 16; b++) {
                    float v = acc[g][b];
                    #pragma unroll
                    for (int o = 16; o; o >>= 1)
                        v += __shfl_xor_sync(0xffffffffu, v, o);
                    if (lane == b) gate[g] = v;
                }

            if (lane < 16) {
                const float* pb = pre + (size_t)t * 65536 + (size_t)lane * 4096;
                float ig = sigf(gate[0] + pb[hh]);
                float fg = sigf(gate[1] + pb[1024 + hh]);
                float gg = tanhf(gate[2] + pb[2048 + hh]);
                float og = sigf(gate[3] + pb[3072 + hh]);
                c = fg * c + ig * gg;
                float hv = og * tanhf(c);
                hdst[lane * 1024 + hh] = hv;
                hout[(size_t)t * 16384 + lane * 1024 + hh] = hv;
            }
        }

        // ---- grid barrier (sense via monotonically increasing generation) ----
        __syncthreads();
        if (tid == 0) {
            __threadfence();
            unsigned prev = atomicAdd(&g_bar_count, 1u);
            if (prev == 147u) {
                atomicExch(&g_bar_count, 0u);
                __threadfence();
                atomicExch(&g_bar_gen, (unsigned)(t + 1));
            } else {
                while (*(volatile unsigned*)&g_bar_gen < (unsigned)(t + 1))
                    __nanosleep(32);
            }
            __threadfence();
        }
        // __syncthreads at top of next iteration releases the block.
    }
}

// ---------------------------------------------------------------------------
// Orchestration
// ---------------------------------------------------------------------------
extern "C" void kernel_launch(void* const* d_in, const int* in_sizes, int n_in,
                              void* d_out, int out_size)
{
    const float* x    = (const float*)d_in[0];
    const float* w0   = (const float*)d_in[1];
    const float* vc0  = (const float*)d_in[2];
    const float* b0   = (const float*)d_in[3];
    const float* g0   = (const float*)d_in[4];
    const float* be0  = (const float*)d_in[5];
    const float* Ws   = (const float*)d_in[6];
    const float* VCs  = (const float*)d_in[7];
    const float* Bsb  = (const float*)d_in[8];
    const float* Gs   = (const float*)d_in[9];
    const float* Bes  = (const float*)d_in[10];
    const float* Wih  = (const float*)d_in[11];
    const float* Whh  = (const float*)d_in[12];
    const float* bih  = (const float*)d_in[13];
    const float* bhh  = (const float*)d_in[14];
    const float* gh   = (const float*)d_in[15];
    const float* bhv  = (const float*)d_in[16];
    const float* Wout = (const float*)d_in[17];
    float* out = (float*)d_out;

    float *xn, *U, *hA, *hB, *WihT, *bsum, *h0, *h1;
    cudaGetSymbolAddress((void**)&xn,    g_xn);
    cudaGetSymbolAddress((void**)&U,     g_U);
    cudaGetSymbolAddress((void**)&hA,    g_hA);
    cudaGetSymbolAddress((void**)&hB,    g_hB);
    cudaGetSymbolAddress((void**)&WihT,  g_WihT);
    cudaGetSymbolAddress((void**)&bsum,  g_bsum);
    cudaGetSymbolAddress((void**)&h0,    g_h0);
    cudaGetSymbolAddress((void**)&h1,    g_h1);

    cudaFuncSetAttribute(lstm_persist, cudaFuncAttributeMaxDynamicSharedMemorySize, 65536);

    const int B = 16, H = 1024;

    // ---- SRU layer 0: (B,1024,128) -> (1024,B,1024) ----
    ln_rows<<<16384, 256>>>(x, xn, g0, be0, 1024, B, 128, 1, 0);
    { dim3 g(32, 128); sgemm<<<g, 256>>>(xn, w0, nullptr, U, 16384, 4096, 128); }
    sru_scan<<<64, 256>>>(U, nullptr, vc0, b0, hA, 1024, B, H, 4);

    float* cur = hA; float* alt = hB;

    // ---- SRU layers 1-3 (L=1024) ----
    for (int i = 0; i < 3; i++) {
        ln_rows<<<16384, 256>>>(cur, xn, Gs + i * H, Bes + i * H, 1024, B, H, 0, 0);
        dim3 g(24, 128);
        sgemm<<<g, 256>>>(xn, Ws + (size_t)i * H * 3072, nullptr, U, 16384, 3072, 1024);
        sru_scan<<<64, 256>>>(U, xn, VCs + i * 2048, Bsb + i * 2048, alt, 1024, B, H, 3);
        float* t2 = cur; cur = alt; alt = t2;
    }

    // ---- time pooling 1024 -> 512 ----
    pool2<<<32768, 256>>>(cur, alt, 512 * 16 * 1024);
    { float* t2 = cur; cur = alt; alt = t2; }

    // ---- SRU layers 4-6 (L=512) ----
    for (int i = 3; i < 6; i++) {
        ln_rows<<<8192, 256>>>(cur, xn, Gs + i * H, Bes + i * H, 512, B, H, 0, 0);
        dim3 g(24, 64);
        sgemm<<<g, 256>>>(xn, Ws + (size_t)i * H * 3072, nullptr, U, 8192, 3072, 1024);
        sru_scan<<<64, 256>>>(U, xn, VCs + i * 2048, Bsb + i * 2048, alt, 512, B, H, 3);
        float* t2 = cur; cur = alt; alt = t2;
    }

    // ---- LSTM: pre-GEMM then one persistent kernel for all 512 steps ----
    { dim3 g(32, 128); dim3 bl(32, 8); transpose_k<<<g, bl>>>(Wih, WihT, 4096, 1024); }
    addvec<<<16, 256>>>(bih, bhh, bsum, 4096);
    { dim3 g(32, 64); sgemm<<<g, 256>>>(cur, WihT, bsum, U, 8192, 4096, 1024); }
    lstm_init<<<64, 256>>>(h0);
    lstm_persist<<<148, 256, 65536>>>(U, Whh, h0, h1, alt);

    // ---- final LN (written (b,l)-major) + projection to (16,512,1001) ----
    ln_rows<<<8192, 256>>>(alt, xn, gh, bhv, 512, B, H, 0, 1);
    { dim3 g(8, 64); sgemm<<<g, 256>>>(xn, Wout, nullptr, out, 8192, 1001, 1024); }
}

// round 5
// speedup vs baseline: 1.6941x; 1.6941x over previous
#include <cuda_runtime.h>
#include <cuda_bf16.h>
#include <cstdint>
#include <cstddef>

// ---------------------------------------------------------------------------
// Scratch (device globals; no allocation allowed anywhere)
// ---------------------------------------------------------------------------
__device__ float g_xn [16777216];   // max 16384 rows x 1024
__device__ float g_U  [67108864];   // 1024*16*4096
__device__ float g_hA [16777216];
__device__ float g_hB [16777216];
__device__ float g_bsum[4096];
__device__ float g_h0 [16384];
__device__ float g_h1 [16384];
__device__ unsigned g_bar_count;
__device__ unsigned g_bar_gen;
__device__ __nv_bfloat16 g_Ah[16777216];  // activation hi split
__device__ __nv_bfloat16 g_Al[16777216];  // activation lo split
__device__ __nv_bfloat16 g_Bh[4194304];   // weight hi split [Npad][K]
__device__ __nv_bfloat16 g_Bl[4194304];   // weight lo split

#define LN_EPS 1e-5f

__device__ __forceinline__ float sigf(float x) {
    return __fdividef(1.f, 1.f + __expf(-x));
}

__device__ __forceinline__ uint32_t smem_to_u32(const void* p) {
    uint32_t a;
    asm("{ .reg .u64 t; cvta.to.shared.u64 t, %1; cvt.u32.u64 %0, t; }"
        : "=r"(a) : "l"(p));
    return a;
}

// ---------------------------------------------------------------------------
// mma.sync / ldmatrix / cp.async primitives (base sm_103 target, no tcgen05)
// ---------------------------------------------------------------------------
__device__ __forceinline__ void ldm_x4(uint32_t* r, uint32_t addr) {
    asm volatile("ldmatrix.sync.aligned.m8n8.x4.shared.b16 {%0,%1,%2,%3}, [%4];"
                 : "=r"(r[0]), "=r"(r[1]), "=r"(r[2]), "=r"(r[3]) : "r"(addr));
}
__device__ __forceinline__ void mma_bf16(float* d, const uint32_t* a,
                                         uint32_t b0, uint32_t b1) {
    asm volatile(
        "mma.sync.aligned.m16n8k16.row.col.f32.bf16.bf16.f32 "
        "{%0,%1,%2,%3}, {%4,%5,%6,%7}, {%8,%9}, {%0,%1,%2,%3};"
        : "+f"(d[0]), "+f"(d[1]), "+f"(d[2]), "+f"(d[3])
        : "r"(a[0]), "r"(a[1]), "r"(a[2]), "r"(a[3]), "r"(b0), "r"(b1));
}
__device__ __forceinline__ void cp_async16(uint32_t saddr, const void* gptr) {
    asm volatile("cp.async.cg.shared.global [%0], [%1], 16;"
                 :: "r"(saddr), "l"(__cvta_generic_to_global(gptr)));
}
#define CP_COMMIT()  asm volatile("cp.async.commit_group;" ::: "memory")
#define CP_WAIT(n)   asm volatile("cp.async.wait_group %0;" :: "n"(n) : "memory")

// ---------------------------------------------------------------------------
// Block reduction helper (256-thread blocks)
// ---------------------------------------------------------------------------
__device__ __forceinline__ float blockReduceSum(float v, float* shm) {
    int lane = threadIdx.x & 31, wid = threadIdx.x >> 5;
    #pragma unroll
    for (int o = 16; o; o >>= 1) v += __shfl_xor_sync(0xffffffffu, v, o);
    if (lane == 0) shm[wid] = v;
    __syncthreads();
    int nw = (blockDim.x + 31) >> 5;
    float r = (threadIdx.x < nw) ? shm[threadIdx.x] : 0.f;
    if (wid == 0) {
        #pragma unroll
        for (int o = 16; o; o >>= 1) r += __shfl_xor_sync(0xffffffffu, r, o);
        if (lane == 0) shm[0] = r;
    }
    __syncthreads();
    float total = shm[0];
    __syncthreads();
    return total;
}

// ---------------------------------------------------------------------------
// LayerNorm over last dim.
// ---------------------------------------------------------------------------
__global__ __launch_bounds__(256) void ln_rows(
    const float* __restrict__ src, float* __restrict__ dst,
    const float* __restrict__ g, const float* __restrict__ be,
    int L, int Bb, int D, int srcBMajor, int dstBMajor)
{
    __shared__ float shm[32];
    int r = blockIdx.x;
    int l = r / Bb, b = r % Bb;
    const float* s = src + (srcBMajor ? ((size_t)b * L + l) : (size_t)r) * D;
    float*       d = dst + (dstBMajor ? ((size_t)b * L + l) : (size_t)r) * D;

    float sum = 0.f;
    for (int i = threadIdx.x; i < D; i += 256) sum += s[i];
    float mean = blockReduceSum(sum, shm) / (float)D;

    float vs = 0.f;
    for (int i = threadIdx.x; i < D; i += 256) { float t = s[i] - mean; vs += t * t; }
    float var = blockReduceSum(vs, shm) / (float)D;
    float rstd = rsqrtf(var + LN_EPS);

    for (int i = threadIdx.x; i < D; i += 256)
        d[i] = (s[i] - mean) * rstd * g[i] + be[i];
}

// ---------------------------------------------------------------------------
// Split conversion: fp32 -> (bf16 hi, bf16 lo)
// ---------------------------------------------------------------------------
__global__ void conv_split(const float* __restrict__ x,
                           __nv_bfloat16* __restrict__ hi,
                           __nv_bfloat16* __restrict__ lo, int n)
{
    int i = blockIdx.x * blockDim.x + threadIdx.x;
    if (i >= n) return;
    float v = x[i];
    __nv_bfloat16 h = __float2bfloat16(v);
    hi[i] = h;
    lo[i] = __float2bfloat16(v - __bfloat162float(h));
}

// W[K][N] -> Bh/Bl [Npad][K] (zero rows for n >= N). grid (Npad/32, K/32), block (32,8)
__global__ void transpose_split(const float* __restrict__ W,
                                __nv_bfloat16* __restrict__ Bh,
                                __nv_bfloat16* __restrict__ Bl,
                                int K, int N)
{
    __shared__ float t[32][33];
    int n0 = blockIdx.x * 32, k0 = blockIdx.y * 32;
    int x = threadIdx.x, y = threadIdx.y;
    #pragma unroll
    for (int j = 0; j < 32; j += 8) {
        int k = k0 + y + j, n = n0 + x;
        t[y + j][x] = (n < N) ? W[(size_t)k * N + n] : 0.f;
    }
    __syncthreads();
    #pragma unroll
    for (int j = 0; j < 32; j += 8) {
        int n = n0 + y + j, k = k0 + x;
        float v = t[x][y + j];
        __nv_bfloat16 h = __float2bfloat16(v);
        Bh[(size_t)n * K + k] = h;
        Bl[(size_t)n * K + k] = __float2bfloat16(v - __bfloat162float(h));
    }
}

// ---------------------------------------------------------------------------
// Split-bf16 GEMM via mma.sync: C[M][ldC] = A[M][K] @ (B[Npad][K])^T (+bias)
// D += Ah*Bh + Ah*Bl + Al*Bh  (fp32 accum).
// CTA 128x128, BK=32, 8 warps (2x4), warp tile 64x32, cp.async double buffer.
// smem rows padded to 80 B -> conflict-free ldmatrix.
// ---------------------------------------------------------------------------
#define GS_A_LO  10240
#define GS_B_HI  20480
#define GS_B_LO  30720
#define GS_STAGE 40960

__global__ __launch_bounds__(256, 1) void gemm_mma(
    const __nv_bfloat16* __restrict__ Ah, const __nv_bfloat16* __restrict__ Al,
    const __nv_bfloat16* __restrict__ Bh, const __nv_bfloat16* __restrict__ Bl,
    const float* __restrict__ bias, float* __restrict__ C,
    int K, int Nreal, int ldC)
{
    extern __shared__ char smem[];
    const uint32_t sb = smem_to_u32(smem);
    const int tid = threadIdx.x, warp = tid >> 5, lane = tid & 31;
    const int n0 = blockIdx.x * 128, m0 = blockIdx.y * 128;
    const int warpM = warp >> 2, warpN = warp & 3;      // 2 x 4
    const int S = K >> 5;                                // BK = 32

    float d[4][4][4];
    #pragma unroll
    for (int mt = 0; mt < 4; mt++)
        #pragma unroll
        for (int nt = 0; nt < 4; nt++)
            #pragma unroll
            for (int e = 0; e < 4; e++) d[mt][nt][e] = 0.f;

    // stage loader: 4 arrays x 128 rows x 4 16B-chunks, 2 chunks/thread/array
    auto load_stage = [&](int s, int buf) {
        const size_t kc = (size_t)s << 5;
        #pragma unroll
        for (int i = 0; i < 2; i++) {
            int idx = tid + i * 256;            // 0..511
            int row = idx >> 2, c = idx & 3;
            uint32_t so = (uint32_t)buf * GS_STAGE + row * 80 + c * 16;
            size_t ga = (size_t)(m0 + row) * K + kc + c * 8;
            size_t gb = (size_t)(n0 + row) * K + kc + c * 8;
            cp_async16(sb + so,           Ah + ga);
            cp_async16(sb + so + GS_A_LO, Al + ga);
            cp_async16(sb + so + GS_B_HI, Bh + gb);
            cp_async16(sb + so + GS_B_LO, Bl + gb);
        }
        CP_COMMIT();
    };

    load_stage(0, 0);

    for (int s = 0; s < S; s++) {
        const int buf = s & 1;
        if (s + 1 < S) load_stage(s + 1, buf ^ 1);
        if (s + 1 < S) { CP_WAIT(1); } else { CP_WAIT(0); }
        __syncthreads();

        const uint32_t aBase = sb + (uint32_t)buf * GS_STAGE + (warpM * 64) * 80;
        const uint32_t bBase = sb + (uint32_t)buf * GS_STAGE + GS_B_HI + (warpN * 32) * 80;
        // per-lane ldmatrix addressing: row = l&15, 16B col = l>>4
        const uint32_t aOff = (uint32_t)(lane & 15) * 80 + (uint32_t)(lane >> 4) * 16;
        const uint32_t bOff = aOff;

        #pragma unroll
        for (int ks = 0; ks < 2; ks++) {
            const uint32_t kb = (uint32_t)ks * 32;
            uint32_t aH[4][4], aL[4][4], bH[2][4], bL[2][4];
            #pragma unroll
            for (int mt = 0; mt < 4; mt++) {
                uint32_t ad = aBase + (uint32_t)(mt * 16) * 80 + kb + aOff;
                ldm_x4(aH[mt], ad);
                ldm_x4(aL[mt], ad + GS_A_LO);
            }
            #pragma unroll
            for (int ng = 0; ng < 2; ng++) {
                uint32_t bd = bBase + (uint32_t)(ng * 16) * 80 + kb + bOff;
                ldm_x4(bH[ng], bd);
                ldm_x4(bL[ng], bd + (GS_B_LO - GS_B_HI));
            }
            #pragma unroll
            for (int mt = 0; mt < 4; mt++)
                #pragma unroll
                for (int ng = 0; ng < 2; ng++) {
                    mma_bf16(d[mt][2 * ng],     aH[mt], bH[ng][0], bH[ng][2]);
                    mma_bf16(d[mt][2 * ng + 1], aH[mt], bH[ng][1], bH[ng][3]);
                    mma_bf16(d[mt][2 * ng],     aH[mt], bL[ng][0], bL[ng][2]);
                    mma_bf16(d[mt][2 * ng + 1], aH[mt], bL[ng][1], bL[ng][3]);
                    mma_bf16(d[mt][2 * ng],     aL[mt], bH[ng][0], bH[ng][2]);
                    mma_bf16(d[mt][2 * ng + 1], aL[mt], bH[ng][1], bH[ng][3]);
                }
        }
        __syncthreads();
    }

    // epilogue: thread (lane) owns rows (lane>>2, +8), cols (lane&3)*2 (+1)
    const int r0 = m0 + warpM * 64 + (lane >> 2);
    const int c0 = n0 + warpN * 32 + (lane & 3) * 2;
    #pragma unroll
    for (int mt = 0; mt < 4; mt++) {
        #pragma unroll
        for (int nt = 0; nt < 4; nt++) {
            int cc = c0 + nt * 8;
            float* p0 = C + (size_t)(r0 + mt * 16) * ldC;
            float* p1 = p0 + 8 * (size_t)ldC;
            if (cc < Nreal) {
                float bv = bias ? bias[cc] : 0.f;
                p0[cc] = d[mt][nt][0] + bv;
                p1[cc] = d[mt][nt][2] + bv;
            }
            if (cc + 1 < Nreal) {
                float bv = bias ? bias[cc + 1] : 0.f;
                p0[cc + 1] = d[mt][nt][1] + bv;
                p1[cc + 1] = d[mt][nt][3] + bv;
            }
        }
    }
}

// ---------------------------------------------------------------------------
// SRU scan: 16384 independent recurrences.
// ---------------------------------------------------------------------------
__global__ void sru_scan(
    const float* __restrict__ U, const float* __restrict__ res,
    const float* __restrict__ vc, const float* __restrict__ bias,
    float* __restrict__ out, int L, int Bb, int H, int k)
{
    int idx = blockIdx.x * blockDim.x + threadIdx.x;
    if (idx >= Bb * H) return;
    int hh = idx % H, b = idx / H;
    float vf = vc[hh], vr = vc[H + hh];
    float bf = bias[hh], br = bias[H + hh];
    float c = 0.f;

    size_t ustep = (size_t)Bb * k * H;
    size_t ubase = (size_t)b * k * H + hh;
    size_t ostep = (size_t)Bb * H;
    size_t obase = (size_t)b * H + hh;

    const float* u  = U + ubase;
    const float* rp = (k == 3) ? (res + obase) : (U + ubase + 3 * (size_t)H);
    size_t rstep    = (k == 3) ? ostep : ustep;
    float* o = out + obase;

    for (int t = 0; t < L; ++t) {
        float a0 = u[0], a1 = u[H], a2 = u[2 * (size_t)H];
        float rt = rp[0];
        float f = sigf(a1 + vf * c + bf);
        float r = sigf(a2 + vr * c + br);
        c = f * c + (1.f - f) * a0;
        o[0] = r * c + (1.f - r) * rt;
        u += ustep; rp += rstep; o += ostep;
    }
}

__global__ void pool2(const float* __restrict__ in, float* __restrict__ out, int n)
{
    int i = blockIdx.x * blockDim.x + threadIdx.x;
    if (i >= n) return;
    int lp = i >> 14;
    size_t j = (size_t)i + (size_t)lp * 16384;
    out[i] = 0.5f * (in[j] + in[j + 16384]);
}

__global__ void addvec(const float* __restrict__ a, const float* __restrict__ b,
                       float* __restrict__ o, int n)
{
    int i = blockIdx.x * blockDim.x + threadIdx.x;
    if (i < n) o[i] = a[i] + b[i];
}

__global__ void lstm_init(float* h0)
{
    int i = blockIdx.x * blockDim.x + threadIdx.x;
    if (i < 16384) h0[i] = 0.f;
    if (i == 0) { g_bar_count = 0u; g_bar_gen = 0u; }
}

// ---------------------------------------------------------------------------
// Persistent LSTM (148 CTAs, grid barrier per step)
// ---------------------------------------------------------------------------
__global__ __launch_bounds__(256) void lstm_persist(
    const float* __restrict__ pre, const float* __restrict__ Whh,
    float* __restrict__ hbuf0, float* __restrict__ hbuf1,
    float* __restrict__ hout)
{
    extern __shared__ float hs[];
    float4* hs4 = (float4*)hs;
    const int tid = threadIdx.x, bid = blockIdx.x;
    const int warp = tid >> 5, lane = tid & 31;

    int cnt, s;
    if (bid < 136) { cnt = 7; s = bid * 7; }
    else           { cnt = 6; s = 952 + (bid - 136) * 6; }
    const bool active = warp < cnt;
    const int hh = s + (active ? warp : 0);

    const float4* W4[4];
    #pragma unroll
    for (int g = 0; g < 4; g++)
        W4[g] = (const float4*)(Whh + ((size_t)g * 1024 + hh) * 1024);

    float c = 0.f;

    for (int t = 0; t < 512; t++) {
        const float4* hsrc = (const float4*)((t & 1) ? hbuf1 : hbuf0);
        float*        hdst = (t & 1) ? hbuf0 : hbuf1;

        __syncthreads();
        for (int i = tid; i < 4096; i += 256) hs4[i] = __ldcg(hsrc + i);
        __syncthreads();

        if (active) {
            float acc[4][16];
            #pragma unroll
            for (int g = 0; g < 4; g++)
                #pragma unroll
                for (int b = 0; b < 16; b++) acc[g][b] = 0.f;

            #pragma unroll 1
            for (int i = lane; i < 256; i += 32) {
                float4 wv[4];
                #pragma unroll
                for (int g = 0; g < 4; g++) wv[g] = W4[g][i];
                #pragma unroll
                for (int b = 0; b < 16; b++) {
                    float4 hv = hs4[b * 256 + i];
                    #pragma unroll
                    for (int g = 0; g < 4; g++)
                        acc[g][b] += wv[g].x * hv.x + wv[g].y * hv.y
                                   + wv[g].z * hv.z + wv[g].w * hv.w;
                }
            }

            float gate[4] = {0.f, 0.f, 0.f, 0.f};
            #pragma unroll
            for (int g = 0; g < 4; g++)
                #pragma unroll
                for (int b = 0; b < 16; b++) {
                    float v = acc[g][b];
                    #pragma unroll
                    for (int o = 16; o; o >>= 1)
                        v += __shfl_xor_sync(0xffffffffu, v, o);
                    if (lane == b) gate[g] = v;
                }

            if (lane < 16) {
                const float* pb = pre + (size_t)t * 65536 + (size_t)lane * 4096;
                float ig = sigf(gate[0] + pb[hh]);
                float fg = sigf(gate[1] + pb[1024 + hh]);
                float gg = tanhf(gate[2] + pb[2048 + hh]);
                float og = sigf(gate[3] + pb[3072 + hh]);
                c = fg * c + ig * gg;
                float hv = og * tanhf(c);
                hdst[lane * 1024 + hh] = hv;
                hout[(size_t)t * 16384 + lane * 1024 + hh] = hv;
            }
        }

        __syncthreads();
        if (tid == 0) {
            __threadfence();
            unsigned prev = atomicAdd(&g_bar_count, 1u);
            if (prev == 147u) {
                atomicExch(&g_bar_count, 0u);
                __threadfence();
                atomicExch(&g_bar_gen, (unsigned)(t + 1));
            } else {
                while (*(volatile unsigned*)&g_bar_gen < (unsigned)(t + 1))
                    __nanosleep(32);
            }
            __threadfence();
        }
    }
}

// ---------------------------------------------------------------------------
// Orchestration
// ---------------------------------------------------------------------------
extern "C" void kernel_launch(void* const* d_in, const int* in_sizes, int n_in,
                              void* d_out, int out_size)
{
    const float* x    = (const float*)d_in[0];
    const float* w0   = (const float*)d_in[1];
    const float* vc0  = (const float*)d_in[2];
    const float* b0   = (const float*)d_in[3];
    const float* g0   = (const float*)d_in[4];
    const float* be0  = (const float*)d_in[5];
    const float* Ws   = (const float*)d_in[6];
    const float* VCs  = (const float*)d_in[7];
    const float* Bsb  = (const float*)d_in[8];
    const float* Gs   = (const float*)d_in[9];
    const float* Bes  = (const float*)d_in[10];
    const float* Wih  = (const float*)d_in[11];
    const float* Whh  = (const float*)d_in[12];
    const float* bih  = (const float*)d_in[13];
    const float* bhh  = (const float*)d_in[14];
    const float* gh   = (const float*)d_in[15];
    const float* bhv  = (const float*)d_in[16];
    const float* Wout = (const float*)d_in[17];
    float* out = (float*)d_out;

    float *xn, *U, *hA, *hB, *bsum, *h0, *h1;
    __nv_bfloat16 *Ah, *Al, *Bh, *Bl;
    cudaGetSymbolAddress((void**)&xn,   g_xn);
    cudaGetSymbolAddress((void**)&U,    g_U);
    cudaGetSymbolAddress((void**)&hA,   g_hA);
    cudaGetSymbolAddress((void**)&hB,   g_hB);
    cudaGetSymbolAddress((void**)&bsum, g_bsum);
    cudaGetSymbolAddress((void**)&h0,   g_h0);
    cudaGetSymbolAddress((void**)&h1,   g_h1);
    cudaGetSymbolAddress((void**)&Ah,   g_Ah);
    cudaGetSymbolAddress((void**)&Al,   g_Al);
    cudaGetSymbolAddress((void**)&Bh,   g_Bh);
    cudaGetSymbolAddress((void**)&Bl,   g_Bl);

    cudaFuncSetAttribute(lstm_persist, cudaFuncAttributeMaxDynamicSharedMemorySize, 65536);
    cudaFuncSetAttribute(gemm_mma,    cudaFuncAttributeMaxDynamicSharedMemorySize, 2 * GS_STAGE);

    const int B = 16, H = 1024;
    const int GSM = 2 * GS_STAGE;

    // ---- SRU layer 0: (B,1024,128) -> (1024,B,1024) ----
    ln_rows<<<16384, 256>>>(x, xn, g0, be0, 1024, B, 128, 1, 0);
    conv_split<<<8192, 256>>>(xn, Ah, Al, 16384 * 128);
    { dim3 g(4096 / 32, 128 / 32); dim3 bl(32, 8);
      transpose_split<<<g, bl>>>(w0, Bh, Bl, 128, 4096); }
    { dim3 g(32, 128); gemm_mma<<<g, 256, GSM>>>(Ah, Al, Bh, Bl, nullptr, U, 128, 4096, 4096); }
    sru_scan<<<64, 256>>>(U, nullptr, vc0, b0, hA, 1024, B, H, 4);

    float* cur = hA; float* alt = hB;

    // ---- SRU layers 1-3 (L=1024) ----
    for (int i = 0; i < 3; i++) {
        ln_rows<<<16384, 256>>>(cur, xn, Gs + i * H, Bes + i * H, 1024, B, H, 0, 0);
        conv_split<<<65536, 256>>>(xn, Ah, Al, 16384 * 1024);
        { dim3 g(3072 / 32, 1024 / 32); dim3 bl(32, 8);
          transpose_split<<<g, bl>>>(Ws + (size_t)i * H * 3072, Bh, Bl, 1024, 3072); }
        { dim3 g(24, 128); gemm_mma<<<g, 256, GSM>>>(Ah, Al, Bh, Bl, nullptr, U, 1024, 3072, 3072); }
        sru_scan<<<64, 256>>>(U, xn, VCs + i * 2048, Bsb + i * 2048, alt, 1024, B, H, 3);
        float* t2 = cur; cur = alt; alt = t2;
    }

    // ---- time pooling 1024 -> 512 ----
    pool2<<<32768, 256>>>(cur, alt, 512 * 16 * 1024);
    { float* t2 = cur; cur = alt; alt = t2; }

    // ---- SRU layers 4-6 (L=512) ----
    for (int i = 3; i < 6; i++) {
        ln_rows<<<8192, 256>>>(cur, xn, Gs + i * H, Bes + i * H, 512, B, H, 0, 0);
        conv_split<<<32768, 256>>>(xn, Ah, Al, 8192 * 1024);
        { dim3 g(3072 / 32, 1024 / 32); dim3 bl(32, 8);
          transpose_split<<<g, bl>>>(Ws + (size_t)i * H * 3072, Bh, Bl, 1024, 3072); }
        { dim3 g(24, 64); gemm_mma<<<g, 256, GSM>>>(Ah, Al, Bh, Bl, nullptr, U, 1024, 3072, 3072); }
        sru_scan<<<64, 256>>>(U, xn, VCs + i * 2048, Bsb + i * 2048, alt, 512, B, H, 3);
        float* t2 = cur; cur = alt; alt = t2;
    }

    // ---- LSTM: pre-GEMM (Wih already [4096,1024] = B layout) ----
    addvec<<<16, 256>>>(bih, bhh, bsum, 4096);
    conv_split<<<32768, 256>>>(cur, Ah, Al, 8192 * 1024);
    conv_split<<<16384, 256>>>(Wih, Bh, Bl, 4096 * 1024);
    { dim3 g(32, 64); gemm_mma<<<g, 256, GSM>>>(Ah, Al, Bh, Bl, bsum, U, 1024, 4096, 4096); }
    lstm_init<<<64, 256>>>(h0);
    lstm_persist<<<148, 256, 65536>>>(U, Whh, h0, h1, alt);

    // ---- final LN (written (b,l)-major) + projection to (16,512,1001) ----
    ln_rows<<<8192, 256>>>(alt, xn, gh, bhv, 512, B, H, 0, 1);
    conv_split<<<32768, 256>>>(xn, Ah, Al, 8192 * 1024);
    { dim3 g(1024 / 32, 1024 / 32); dim3 bl(32, 8);
      transpose_split<<<g, bl>>>(Wout, Bh, Bl, 1024, 1001); }
    { dim3 g(8, 64); gemm_mma<<<g, 256, GSM>>>(Ah, Al, Bh, Bl, nullptr, out, 1024, 1001, 1001); }
}

// round 6
// speedup vs baseline: 1.8294x; 1.0799x over previous
#include <cuda_runtime.h>
#include <cuda_bf16.h>
#include <cstdint>
#include <cstddef>

// ---------------------------------------------------------------------------
// Scratch (device globals; no allocation allowed anywhere)
// ---------------------------------------------------------------------------
__device__ float g_xn [16777216];   // max 16384 rows x 1024
__device__ float g_U  [67108864];   // 1024*16*4096
__device__ float g_hA [16777216];
__device__ float g_hB [16777216];
__device__ float g_bsum[4096];
__device__ float g_h0 [16384];
__device__ float g_h1 [16384];
__device__ unsigned g_bar_count;
__device__ unsigned g_bar_gen;
__device__ __nv_bfloat16 g_Ah[16777216];  // activation hi split
__device__ __nv_bfloat16 g_Al[16777216];  // activation lo split
__device__ __nv_bfloat16 g_Bh[4194304];   // weight hi split [Npad][K]
__device__ __nv_bfloat16 g_Bl[4194304];   // weight lo split

#define LN_EPS 1e-5f

__device__ __forceinline__ float sigf(float x) {
    return __fdividef(1.f, 1.f + __expf(-x));
}

__device__ __forceinline__ uint32_t smem_to_u32(const void* p) {
    uint32_t a;
    asm("{ .reg .u64 t; cvta.to.shared.u64 t, %1; cvt.u32.u64 %0, t; }"
        : "=r"(a) : "l"(p));
    return a;
}

// ---------------------------------------------------------------------------
// mma.sync / ldmatrix / cp.async primitives (base sm_103 target)
// ---------------------------------------------------------------------------
__device__ __forceinline__ void ldm_x4(uint32_t* r, uint32_t addr) {
    asm volatile("ldmatrix.sync.aligned.m8n8.x4.shared.b16 {%0,%1,%2,%3}, [%4];"
                 : "=r"(r[0]), "=r"(r[1]), "=r"(r[2]), "=r"(r[3]) : "r"(addr));
}
__device__ __forceinline__ void mma_bf16(float* d, const uint32_t* a,
                                         uint32_t b0, uint32_t b1) {
    asm volatile(
        "mma.sync.aligned.m16n8k16.row.col.f32.bf16.bf16.f32 "
        "{%0,%1,%2,%3}, {%4,%5,%6,%7}, {%8,%9}, {%0,%1,%2,%3};"
        : "+f"(d[0]), "+f"(d[1]), "+f"(d[2]), "+f"(d[3])
        : "r"(a[0]), "r"(a[1]), "r"(a[2]), "r"(a[3]), "r"(b0), "r"(b1));
}
__device__ __forceinline__ void cp_async16(uint32_t saddr, const void* gptr) {
    asm volatile("cp.async.cg.shared.global [%0], [%1], 16;"
                 :: "r"(saddr), "l"(__cvta_generic_to_global(gptr)));
}
#define CP_COMMIT()  asm volatile("cp.async.commit_group;" ::: "memory")
#define CP_WAIT(n)   asm volatile("cp.async.wait_group %0;" :: "n"(n) : "memory")

// ---------------------------------------------------------------------------
// Block reduction helper (256-thread blocks)
// ---------------------------------------------------------------------------
__device__ __forceinline__ float blockReduceSum(float v, float* shm) {
    int lane = threadIdx.x & 31, wid = threadIdx.x >> 5;
    #pragma unroll
    for (int o = 16; o; o >>= 1) v += __shfl_xor_sync(0xffffffffu, v, o);
    if (lane == 0) shm[wid] = v;
    __syncthreads();
    int nw = (blockDim.x + 31) >> 5;
    float r = (threadIdx.x < nw) ? shm[threadIdx.x] : 0.f;
    if (wid == 0) {
        #pragma unroll
        for (int o = 16; o; o >>= 1) r += __shfl_xor_sync(0xffffffffu, r, o);
        if (lane == 0) shm[0] = r;
    }
    __syncthreads();
    float total = shm[0];
    __syncthreads();
    return total;
}

// ---------------------------------------------------------------------------
// LayerNorm over last dim, fused bf16 hi/lo split output (hi/lo nullable).
// ---------------------------------------------------------------------------
__global__ __launch_bounds__(256) void ln_rows(
    const float* __restrict__ src, float* __restrict__ dst,
    __nv_bfloat16* __restrict__ hi, __nv_bfloat16* __restrict__ lo,
    const float* __restrict__ g, const float* __restrict__ be,
    int L, int Bb, int D, int srcBMajor, int dstBMajor)
{
    __shared__ float shm[32];
    int r = blockIdx.x;
    int l = r / Bb, b = r % Bb;
    const float* s = src + (srcBMajor ? ((size_t)b * L + l) : (size_t)r) * D;
    size_t drow = (dstBMajor ? ((size_t)b * L + l) : (size_t)r) * D;
    float* d = dst + drow;

    float sum = 0.f;
    for (int i = threadIdx.x; i < D; i += 256) sum += s[i];
    float mean = blockReduceSum(sum, shm) / (float)D;

    float vs = 0.f;
    for (int i = threadIdx.x; i < D; i += 256) { float t = s[i] - mean; vs += t * t; }
    float var = blockReduceSum(vs, shm) / (float)D;
    float rstd = rsqrtf(var + LN_EPS);

    for (int i = threadIdx.x; i < D; i += 256) {
        float v = (s[i] - mean) * rstd * g[i] + be[i];
        d[i] = v;
        if (hi) {
            __nv_bfloat16 h = __float2bfloat16(v);
            hi[drow + i] = h;
            lo[drow + i] = __float2bfloat16(v - __bfloat162float(h));
        }
    }
}

// ---------------------------------------------------------------------------
// Split conversion: fp32 -> (bf16 hi, bf16 lo)
// ---------------------------------------------------------------------------
__global__ void conv_split(const float* __restrict__ x,
                           __nv_bfloat16* __restrict__ hi,
                           __nv_bfloat16* __restrict__ lo, int n)
{
    int i = blockIdx.x * blockDim.x + threadIdx.x;
    if (i >= n) return;
    float v = x[i];
    __nv_bfloat16 h = __float2bfloat16(v);
    hi[i] = h;
    lo[i] = __float2bfloat16(v - __bfloat162float(h));
}

// W[K][N] -> Bh/Bl [Npad][K] (zero rows for n >= N). grid (Npad/32, K/32), block (32,8)
__global__ void transpose_split(const float* __restrict__ W,
                                __nv_bfloat16* __restrict__ Bh,
                                __nv_bfloat16* __restrict__ Bl,
                                int K, int N)
{
    __shared__ float t[32][33];
    int n0 = blockIdx.x * 32, k0 = blockIdx.y * 32;
    int x = threadIdx.x, y = threadIdx.y;
    #pragma unroll
    for (int j = 0; j < 32; j += 8) {
        int k = k0 + y + j, n = n0 + x;
        t[y + j][x] = (n < N) ? W[(size_t)k * N + n] : 0.f;
    }
    __syncthreads();
    #pragma unroll
    for (int j = 0; j < 32; j += 8) {
        int n = n0 + y + j, k = k0 + x;
        float v = t[x][y + j];
        __nv_bfloat16 h = __float2bfloat16(v);
        Bh[(size_t)n * K + k] = h;
        Bl[(size_t)n * K + k] = __float2bfloat16(v - __bfloat162float(h));
    }
}

// ---------------------------------------------------------------------------
// Split-bf16 GEMM via mma.sync: C[M][ldC] = A[M][K] @ (B[Npad][K])^T (+bias)
// D += Ah*Bh + Ah*Bl + Al*Bh  (fp32 accum).
// CTA 128x128, BK=16, 8 warps (2x4), warp tile 64x32.
// 4-stage cp.async ring (3-ahead prefetch), 1 syncthreads/stage, 2 CTAs/SM.
// smem rows 48 B (16 elems + 16 pad) -> conflict-free ldmatrix.
// ---------------------------------------------------------------------------
#define GS_A_LO  6144
#define GS_B_HI  12288
#define GS_B_LO  18432
#define GS_STAGE 24576

__global__ __launch_bounds__(256) void gemm_mma(
    const __nv_bfloat16* __restrict__ Ah, const __nv_bfloat16* __restrict__ Al,
    const __nv_bfloat16* __restrict__ Bh, const __nv_bfloat16* __restrict__ Bl,
    const float* __restrict__ bias, float* __restrict__ C,
    int K, int Nreal, int ldC)
{
    extern __shared__ char smem[];
    const uint32_t sb = smem_to_u32(smem);
    const int tid = threadIdx.x, warp = tid >> 5, lane = tid & 31;
    const int n0 = blockIdx.x * 128, m0 = blockIdx.y * 128;
    const int warpM = warp >> 2, warpN = warp & 3;      // 2 x 4
    const int S = K >> 4;                                // BK = 16

    float d[4][4][4];
    #pragma unroll
    for (int mt = 0; mt < 4; mt++)
        #pragma unroll
        for (int nt = 0; nt < 4; nt++)
            #pragma unroll
            for (int e = 0; e < 4; e++) d[mt][nt][e] = 0.f;

    const int lrow = tid >> 1, lc = tid & 1;   // stage loader mapping
    auto load_stage = [&](int s, int buf) {
        const size_t kc = ((size_t)s << 4) + lc * 8;
        uint32_t so = (uint32_t)buf * GS_STAGE + lrow * 48 + lc * 16;
        size_t ga = (size_t)(m0 + lrow) * K + kc;
        size_t gb = (size_t)(n0 + lrow) * K + kc;
        cp_async16(sb + so,           Ah + ga);
        cp_async16(sb + so + GS_A_LO, Al + ga);
        cp_async16(sb + so + GS_B_HI, Bh + gb);
        cp_async16(sb + so + GS_B_LO, Bl + gb);
        CP_COMMIT();
    };

    load_stage(0, 0);
    load_stage(1, 1);
    load_stage(2, 2);

    const uint32_t off = (uint32_t)(lane & 15) * 48 + (uint32_t)(lane >> 4) * 16;

    for (int s = 0; s < S; s++) {
        if (s <= S - 3)      CP_WAIT(2);
        else if (s == S - 2) CP_WAIT(1);
        else                 CP_WAIT(0);
        __syncthreads();
        if (s + 3 < S) load_stage(s + 3, (s + 3) & 3);

        const uint32_t base  = sb + (uint32_t)(s & 3) * GS_STAGE;
        const uint32_t aBase = base + (uint32_t)(warpM * 64) * 48;
        const uint32_t bBase = base + GS_B_HI + (uint32_t)(warpN * 32) * 48;

        uint32_t aH[4][4], aL[4][4], bH[2][4], bL[2][4];
        #pragma unroll
        for (int mt = 0; mt < 4; mt++) {
            uint32_t ad = aBase + (uint32_t)(mt * 16) * 48 + off;
            ldm_x4(aH[mt], ad);
            ldm_x4(aL[mt], ad + GS_A_LO);
        }
        #pragma unroll
        for (int ng = 0; ng < 2; ng++) {
            uint32_t bd = bBase + (uint32_t)(ng * 16) * 48 + off;
            ldm_x4(bH[ng], bd);
            ldm_x4(bL[ng], bd + (GS_B_LO - GS_B_HI));
        }
        #pragma unroll
        for (int mt = 0; mt < 4; mt++)
            #pragma unroll
            for (int ng = 0; ng < 2; ng++) {
                mma_bf16(d[mt][2 * ng],     aH[mt], bH[ng][0], bH[ng][2]);
                mma_bf16(d[mt][2 * ng + 1], aH[mt], bH[ng][1], bH[ng][3]);
                mma_bf16(d[mt][2 * ng],     aH[mt], bL[ng][0], bL[ng][2]);
                mma_bf16(d[mt][2 * ng + 1], aH[mt], bL[ng][1], bL[ng][3]);
                mma_bf16(d[mt][2 * ng],     aL[mt], bH[ng][0], bH[ng][2]);
                mma_bf16(d[mt][2 * ng + 1], aL[mt], bH[ng][1], bH[ng][3]);
            }
        // no trailing sync: next iteration's sync precedes buffer overwrite
    }

    // epilogue: thread (lane) owns rows (lane>>2, +8), cols (lane&3)*2 (+1)
    const int r0 = m0 + warpM * 64 + (lane >> 2);
    const int c0 = n0 + warpN * 32 + (lane & 3) * 2;
    #pragma unroll
    for (int mt = 0; mt < 4; mt++) {
        #pragma unroll
        for (int nt = 0; nt < 4; nt++) {
            int cc = c0 + nt * 8;
            float* p0 = C + (size_t)(r0 + mt * 16) * ldC;
            float* p1 = p0 + 8 * (size_t)ldC;
            if (cc < Nreal) {
                float bv = bias ? bias[cc] : 0.f;
                p0[cc] = d[mt][nt][0] + bv;
                p1[cc] = d[mt][nt][2] + bv;
            }
            if (cc + 1 < Nreal) {
                float bv = bias ? bias[cc + 1] : 0.f;
                p0[cc + 1] = d[mt][nt][1] + bv;
                p1[cc + 1] = d[mt][nt][3] + bv;
            }
        }
    }
}

// ---------------------------------------------------------------------------
// SRU scan: 16384 independent recurrences; 8-deep register prefetch ring
// with streaming loads to maximize MLP on the serial time loop.
// ---------------------------------------------------------------------------
__global__ void sru_scan(
    const float* __restrict__ U, const float* __restrict__ res,
    const float* __restrict__ vc, const float* __restrict__ bias,
    float* __restrict__ out, int L, int Bb, int H, int k)
{
    int idx = blockIdx.x * blockDim.x + threadIdx.x;
    if (idx >= Bb * H) return;
    int hh = idx % H, b = idx / H;
    float vf = vc[hh], vr = vc[H + hh];
    float bf = bias[hh], br = bias[H + hh];
    float c = 0.f;

    size_t ustep = (size_t)Bb * k * H;
    size_t ubase = (size_t)b * k * H + hh;
    size_t ostep = (size_t)Bb * H;
    size_t obase = (size_t)b * H + hh;

    const float* u  = U + ubase;
    const float* rp = (k == 3) ? (res + obase) : (U + ubase + 3 * (size_t)H);
    size_t rstep    = (k == 3) ? ostep : ustep;
    float* o = out + obase;

    float pa0[8], pa1[8], pa2[8], prt[8];
    #pragma unroll
    for (int j = 0; j < 8; j++) {
        size_t uo = (size_t)j * ustep;
        pa0[j] = __ldcs(u + uo);
        pa1[j] = __ldcs(u + uo + H);
        pa2[j] = __ldcs(u + uo + 2 * (size_t)H);
        prt[j] = __ldcs(rp + (size_t)j * rstep);
    }

    #pragma unroll 8
    for (int t = 0; t < L; ++t) {
        int j = t & 7;
        float a0 = pa0[j], a1 = pa1[j], a2 = pa2[j], rt = prt[j];
        int tn = (t + 8 < L) ? (t + 8) : (L - 1);
        size_t uo = (size_t)tn * ustep;
        pa0[j] = __ldcs(u + uo);
        pa1[j] = __ldcs(u + uo + H);
        pa2[j] = __ldcs(u + uo + 2 * (size_t)H);
        prt[j] = __ldcs(rp + (size_t)tn * rstep);

        float f = sigf(a1 + vf * c + bf);
        float r = sigf(a2 + vr * c + br);
        c = f * c + (1.f - f) * a0;
        o[(size_t)t * ostep] = r * c + (1.f - r) * rt;
    }
}

__global__ void pool2(const float* __restrict__ in, float* __restrict__ out, int n)
{
    int i = blockIdx.x * blockDim.x + threadIdx.x;
    if (i >= n) return;
    int lp = i >> 14;
    size_t j = (size_t)i + (size_t)lp * 16384;
    out[i] = 0.5f * (in[j] + in[j + 16384]);
}

__global__ void addvec(const float* __restrict__ a, const float* __restrict__ b,
                       float* __restrict__ o, int n)
{
    int i = blockIdx.x * blockDim.x + threadIdx.x;
    if (i < n) o[i] = a[i] + b[i];
}

__global__ void lstm_init(float* h0)
{
    int i = blockIdx.x * blockDim.x + threadIdx.x;
    if (i < 16384) h0[i] = 0.f;
    if (i == 0) { g_bar_count = 0u; g_bar_gen = 0u; }
}

// ---------------------------------------------------------------------------
// Persistent LSTM (148 CTAs, grid barrier per step)
// ---------------------------------------------------------------------------
__global__ __launch_bounds__(256) void lstm_persist(
    const float* __restrict__ pre, const float* __restrict__ Whh,
    float* __restrict__ hbuf0, float* __restrict__ hbuf1,
    float* __restrict__ hout)
{
    extern __shared__ float hs[];
    float4* hs4 = (float4*)hs;
    const int tid = threadIdx.x, bid = blockIdx.x;
    const int warp = tid >> 5, lane = tid & 31;

    int cnt, s;
    if (bid < 136) { cnt = 7; s = bid * 7; }
    else           { cnt = 6; s = 952 + (bid - 136) * 6; }
    const bool active = warp < cnt;
    const int hh = s + (active ? warp : 0);

    const float4* W4[4];
    #pragma unroll
    for (int g = 0; g < 4; g++)
        W4[g] = (const float4*)(Whh + ((size_t)g * 1024 + hh) * 1024);

    float c = 0.f;

    for (int t = 0; t < 512; t++) {
        const float4* hsrc = (const float4*)((t & 1) ? hbuf1 : hbuf0);
        float*        hdst = (t & 1) ? hbuf0 : hbuf1;

        __syncthreads();
        for (int i = tid; i < 4096; i += 256) hs4[i] = __ldcg(hsrc + i);
        __syncthreads();

        if (active) {
            float acc[4][16];
            #pragma unroll
            for (int g = 0; g < 4; g++)
                #pragma unroll
                for (int b = 0; b < 16; b++) acc[g][b] = 0.f;

            #pragma unroll 1
            for (int i = lane; i < 256; i += 32) {
                float4 wv[4];
                #pragma unroll
                for (int g = 0; g < 4; g++) wv[g] = W4[g][i];
                #pragma unroll
                for (int b = 0; b < 16; b++) {
                    float4 hv = hs4[b * 256 + i];
                    #pragma unroll
                    for (int g = 0; g < 4; g++)
                        acc[g][b] += wv[g].x * hv.x + wv[g].y * hv.y
                                   + wv[g].z * hv.z + wv[g].w * hv.w;
                }
            }

            float gate[4] = {0.f, 0.f, 0.f, 0.f};
            #pragma unroll
            for (int g = 0; g < 4; g++)
                #pragma unroll
                for (int b = 0; b < 16; b++) {
                    float v = acc[g][b];
                    #pragma unroll
                    for (int o = 16; o; o >>= 1)
                        v += __shfl_xor_sync(0xffffffffu, v, o);
                    if (lane == b) gate[g] = v;
                }

            if (lane < 16) {
                const float* pb = pre + (size_t)t * 65536 + (size_t)lane * 4096;
                float ig = sigf(gate[0] + pb[hh]);
                float fg = sigf(gate[1] + pb[1024 + hh]);
                float gg = tanhf(gate[2] + pb[2048 + hh]);
                float og = sigf(gate[3] + pb[3072 + hh]);
                c = fg * c + ig * gg;
                float hv = og * tanhf(c);
                hdst[lane * 1024 + hh] = hv;
                hout[(size_t)t * 16384 + lane * 1024 + hh] = hv;
            }
        }

        __syncthreads();
        if (tid == 0) {
            __threadfence();
            unsigned prev = atomicAdd(&g_bar_count, 1u);
            if (prev == 147u) {
                atomicExch(&g_bar_count, 0u);
                __threadfence();
                atomicExch(&g_bar_gen, (unsigned)(t + 1));
            } else {
                while (*(volatile unsigned*)&g_bar_gen < (unsigned)(t + 1))
                    __nanosleep(32);
            }
            __threadfence();
        }
    }
}

// ---------------------------------------------------------------------------
// Orchestration
// ---------------------------------------------------------------------------
extern "C" void kernel_launch(void* const* d_in, const int* in_sizes, int n_in,
                              void* d_out, int out_size)
{
    const float* x    = (const float*)d_in[0];
    const float* w0   = (const float*)d_in[1];
    const float* vc0  = (const float*)d_in[2];
    const float* b0   = (const float*)d_in[3];
    const float* g0   = (const float*)d_in[4];
    const float* be0  = (const float*)d_in[5];
    const float* Ws   = (const float*)d_in[6];
    const float* VCs  = (const float*)d_in[7];
    const float* Bsb  = (const float*)d_in[8];
    const float* Gs   = (const float*)d_in[9];
    const float* Bes  = (const float*)d_in[10];
    const float* Wih  = (const float*)d_in[11];
    const float* Whh  = (const float*)d_in[12];
    const float* bih  = (const float*)d_in[13];
    const float* bhh  = (const float*)d_in[14];
    const float* gh   = (const float*)d_in[15];
    const float* bhv  = (const float*)d_in[16];
    const float* Wout = (const float*)d_in[17];
    float* out = (float*)d_out;

    float *xn, *U, *hA, *hB, *bsum, *h0, *h1;
    __nv_bfloat16 *Ah, *Al, *Bh, *Bl;
    cudaGetSymbolAddress((void**)&xn,   g_xn);
    cudaGetSymbolAddress((void**)&U,    g_U);
    cudaGetSymbolAddress((void**)&hA,   g_hA);
    cudaGetSymbolAddress((void**)&hB,   g_hB);
    cudaGetSymbolAddress((void**)&bsum, g_bsum);
    cudaGetSymbolAddress((void**)&h0,   g_h0);
    cudaGetSymbolAddress((void**)&h1,   g_h1);
    cudaGetSymbolAddress((void**)&Ah,   g_Ah);
    cudaGetSymbolAddress((void**)&Al,   g_Al);
    cudaGetSymbolAddress((void**)&Bh,   g_Bh);
    cudaGetSymbolAddress((void**)&Bl,   g_Bl);

    cudaFuncSetAttribute(lstm_persist, cudaFuncAttributeMaxDynamicSharedMemorySize, 65536);
    cudaFuncSetAttribute(gemm_mma,    cudaFuncAttributeMaxDynamicSharedMemorySize, 4 * GS_STAGE);

    const int B = 16, H = 1024;
    const int GSM = 4 * GS_STAGE;

    // ---- SRU layer 0: (B,1024,128) -> (1024,B,1024) ----
    ln_rows<<<16384, 256>>>(x, xn, Ah, Al, g0, be0, 1024, B, 128, 1, 0);
    { dim3 g(4096 / 32, 128 / 32); dim3 bl(32, 8);
      transpose_split<<<g, bl>>>(w0, Bh, Bl, 128, 4096); }
    { dim3 g(32, 128); gemm_mma<<<g, 256, GSM>>>(Ah, Al, Bh, Bl, nullptr, U, 128, 4096, 4096); }
    sru_scan<<<64, 256>>>(U, nullptr, vc0, b0, hA, 1024, B, H, 4);

    float* cur = hA; float* alt = hB;

    // ---- SRU layers 1-3 (L=1024) ----
    for (int i = 0; i < 3; i++) {
        ln_rows<<<16384, 256>>>(cur, xn, Ah, Al, Gs + i * H, Bes + i * H, 1024, B, H, 0, 0);
        { dim3 g(3072 / 32, 1024 / 32); dim3 bl(32, 8);
          transpose_split<<<g, bl>>>(Ws + (size_t)i * H * 3072, Bh, Bl, 1024, 3072); }
        { dim3 g(24, 128); gemm_mma<<<g, 256, GSM>>>(Ah, Al, Bh, Bl, nullptr, U, 1024, 3072, 3072); }
        sru_scan<<<64, 256>>>(U, xn, VCs + i * 2048, Bsb + i * 2048, alt, 1024, B, H, 3);
        float* t2 = cur; cur = alt; alt = t2;
    }

    // ---- time pooling 1024 -> 512 ----
    pool2<<<32768, 256>>>(cur, alt, 512 * 16 * 1024);
    { float* t2 = cur; cur = alt; alt = t2; }

    // ---- SRU layers 4-6 (L=512) ----
    for (int i = 3; i < 6; i++) {
        ln_rows<<<8192, 256>>>(cur, xn, Ah, Al, Gs + i * H, Bes + i * H, 512, B, H, 0, 0);
        { dim3 g(3072 / 32, 1024 / 32); dim3 bl(32, 8);
          transpose_split<<<g, bl>>>(Ws + (size_t)i * H * 3072, Bh, Bl, 1024, 3072); }
        { dim3 g(24, 64); gemm_mma<<<g, 256, GSM>>>(Ah, Al, Bh, Bl, nullptr, U, 1024, 3072, 3072); }
        sru_scan<<<64, 256>>>(U, xn, VCs + i * 2048, Bsb + i * 2048, alt, 512, B, H, 3);
        float* t2 = cur; cur = alt; alt = t2;
    }

    // ---- LSTM: pre-GEMM (Wih already [4096,1024] = B layout) ----
    addvec<<<16, 256>>>(bih, bhh, bsum, 4096);
    conv_split<<<32768, 256>>>(cur, Ah, Al, 8192 * 1024);
    conv_split<<<16384, 256>>>(Wih, Bh, Bl, 4096 * 1024);
    { dim3 g(32, 64); gemm_mma<<<g, 256, GSM>>>(Ah, Al, Bh, Bl, bsum, U, 1024, 4096, 4096); }
    lstm_init<<<64, 256>>>(h0);
    lstm_persist<<<148, 256, 65536>>>(U, Whh, h0, h1, alt);

    // ---- final LN (written (b,l)-major) + projection to (16,512,1001) ----
    ln_rows<<<8192, 256>>>(alt, xn, Ah, Al, gh, bhv, 512, B, H, 0, 1);
    { dim3 g(1024 / 32, 1024 / 32); dim3 bl(32, 8);
      transpose_split<<<g, bl>>>(Wout, Bh, Bl, 1024, 1001); }
    { dim3 g(8, 64); gemm_mma<<<g, 256, GSM>>>(Ah, Al, Bh, Bl, nullptr, out, 1024, 1001, 1001); }
}

// round 7
// speedup vs baseline: 1.9007x; 1.0390x over previous
#include <cuda_runtime.h>
#include <cuda_bf16.h>
#include <cstdint>
#include <cstddef>

// ---------------------------------------------------------------------------
// Scratch (device globals; no allocation allowed anywhere)
// ---------------------------------------------------------------------------
__device__ float g_xn [16777216];   // max 16384 rows x 1024
__device__ float g_U  [67108864];   // 1024*16*4096
__device__ float g_hA [16777216];
__device__ float g_hB [16777216];
__device__ float g_bsum[4096];
__device__ float g_h0 [16384];
__device__ float g_h1 [16384];
__device__ unsigned g_bar_count;
__device__ unsigned g_bar_gen;
__device__ __nv_bfloat16 g_Ah[16777216];  // activation hi split
__device__ __nv_bfloat16 g_Al[16777216];  // activation lo split
__device__ __nv_bfloat16 g_Bh[4194304];   // weight hi split [Npad][K]
__device__ __nv_bfloat16 g_Bl[4194304];   // weight lo split

#define LN_EPS 1e-5f

__device__ __forceinline__ float sigf(float x) {
    return __fdividef(1.f, 1.f + __expf(-x));
}

__device__ __forceinline__ uint32_t smem_to_u32(const void* p) {
    uint32_t a;
    asm("{ .reg .u64 t; cvta.to.shared.u64 t, %1; cvt.u32.u64 %0, t; }"
        : "=r"(a) : "l"(p));
    return a;
}

// packed f32x2 fma: acc(lo,hi) += a(lo,hi) * b(lo,hi)
__device__ __forceinline__ void fma_f32x2(unsigned long long& acc,
                                          unsigned long long a,
                                          unsigned long long b) {
    asm("fma.rn.f32x2 %0, %1, %2, %0;" : "+l"(acc) : "l"(a), "l"(b));
}
union F2U { unsigned long long u; float2 f; };

// ---------------------------------------------------------------------------
// mma.sync / ldmatrix / cp.async primitives (base sm_103 target)
// ---------------------------------------------------------------------------
__device__ __forceinline__ void ldm_x4(uint32_t* r, uint32_t addr) {
    asm volatile("ldmatrix.sync.aligned.m8n8.x4.shared.b16 {%0,%1,%2,%3}, [%4];"
                 : "=r"(r[0]), "=r"(r[1]), "=r"(r[2]), "=r"(r[3]) : "r"(addr));
}
__device__ __forceinline__ void mma_bf16(float* d, const uint32_t* a,
                                         uint32_t b0, uint32_t b1) {
    asm volatile(
        "mma.sync.aligned.m16n8k16.row.col.f32.bf16.bf16.f32 "
        "{%0,%1,%2,%3}, {%4,%5,%6,%7}, {%8,%9}, {%0,%1,%2,%3};"
        : "+f"(d[0]), "+f"(d[1]), "+f"(d[2]), "+f"(d[3])
        : "r"(a[0]), "r"(a[1]), "r"(a[2]), "r"(a[3]), "r"(b0), "r"(b1));
}
__device__ __forceinline__ void cp_async16(uint32_t saddr, const void* gptr) {
    asm volatile("cp.async.cg.shared.global [%0], [%1], 16;"
                 :: "r"(saddr), "l"(__cvta_generic_to_global(gptr)));
}
#define CP_COMMIT()  asm volatile("cp.async.commit_group;" ::: "memory")
#define CP_WAIT(n)   asm volatile("cp.async.wait_group %0;" :: "n"(n) : "memory")

// ---------------------------------------------------------------------------
// Block reduction helper (256-thread blocks)
// ---------------------------------------------------------------------------
__device__ __forceinline__ float blockReduceSum(float v, float* shm) {
    int lane = threadIdx.x & 31, wid = threadIdx.x >> 5;
    #pragma unroll
    for (int o = 16; o; o >>= 1) v += __shfl_xor_sync(0xffffffffu, v, o);
    if (lane == 0) shm[wid] = v;
    __syncthreads();
    int nw = (blockDim.x + 31) >> 5;
    float r = (threadIdx.x < nw) ? shm[threadIdx.x] : 0.f;
    if (wid == 0) {
        #pragma unroll
        for (int o = 16; o; o >>= 1) r += __shfl_xor_sync(0xffffffffu, r, o);
        if (lane == 0) shm[0] = r;
    }
    __syncthreads();
    float total = shm[0];
    __syncthreads();
    return total;
}

// ---------------------------------------------------------------------------
// LayerNorm over last dim, fused bf16 hi/lo split output (hi/lo nullable).
// float4-vectorized (D % 4 == 0 guaranteed here: 128 or 1024).
// ---------------------------------------------------------------------------
__global__ __launch_bounds__(256) void ln_rows(
    const float* __restrict__ src, float* __restrict__ dst,
    __nv_bfloat16* __restrict__ hi, __nv_bfloat16* __restrict__ lo,
    const float* __restrict__ g, const float* __restrict__ be,
    int L, int Bb, int D, int srcBMajor, int dstBMajor)
{
    __shared__ float shm[32];
    int r = blockIdx.x;
    int l = r / Bb, b = r % Bb;
    const float* s = src + (srcBMajor ? ((size_t)b * L + l) : (size_t)r) * D;
    size_t drow = (dstBMajor ? ((size_t)b * L + l) : (size_t)r) * D;
    float* d = dst + drow;

    float sum = 0.f;
    for (int i = 4 * threadIdx.x; i < D; i += 1024) {
        float4 v = *(const float4*)(s + i);
        sum += (v.x + v.y) + (v.z + v.w);
    }
    float mean = blockReduceSum(sum, shm) / (float)D;

    float vs = 0.f;
    for (int i = 4 * threadIdx.x; i < D; i += 1024) {
        float4 v = *(const float4*)(s + i);
        float a = v.x - mean, bq = v.y - mean, c = v.z - mean, e = v.w - mean;
        vs += a * a + bq * bq + c * c + e * e;
    }
    float var = blockReduceSum(vs, shm) / (float)D;
    float rstd = rsqrtf(var + LN_EPS);

    for (int i = 4 * threadIdx.x; i < D; i += 1024) {
        float4 v = *(const float4*)(s + i);
        float4 gv = *(const float4*)(g + i);
        float4 bv = *(const float4*)(be + i);
        float4 o;
        o.x = (v.x - mean) * rstd * gv.x + bv.x;
        o.y = (v.y - mean) * rstd * gv.y + bv.y;
        o.z = (v.z - mean) * rstd * gv.z + bv.z;
        o.w = (v.w - mean) * rstd * gv.w + bv.w;
        *(float4*)(d + i) = o;
        if (hi) {
            __nv_bfloat16 h0v = __float2bfloat16(o.x);
            __nv_bfloat16 h1v = __float2bfloat16(o.y);
            __nv_bfloat16 h2v = __float2bfloat16(o.z);
            __nv_bfloat16 h3v = __float2bfloat16(o.w);
            __nv_bfloat162* hp = (__nv_bfloat162*)(hi + drow + i);
            __nv_bfloat162* lp = (__nv_bfloat162*)(lo + drow + i);
            hp[0] = __nv_bfloat162(h0v, h1v);
            hp[1] = __nv_bfloat162(h2v, h3v);
            lp[0] = __nv_bfloat162(
                __float2bfloat16(o.x - __bfloat162float(h0v)),
                __float2bfloat16(o.y - __bfloat162float(h1v)));
            lp[1] = __nv_bfloat162(
                __float2bfloat16(o.z - __bfloat162float(h2v)),
                __float2bfloat16(o.w - __bfloat162float(h3v)));
        }
    }
}

// ---------------------------------------------------------------------------
// Split conversion: fp32 -> (bf16 hi, bf16 lo)
// ---------------------------------------------------------------------------
__global__ void conv_split(const float* __restrict__ x,
                           __nv_bfloat16* __restrict__ hi,
                           __nv_bfloat16* __restrict__ lo, int n)
{
    int i = blockIdx.x * blockDim.x + threadIdx.x;
    if (i >= n) return;
    float v = x[i];
    __nv_bfloat16 h = __float2bfloat16(v);
    hi[i] = h;
    lo[i] = __float2bfloat16(v - __bfloat162float(h));
}

// W[K][N] -> Bh/Bl [Npad][K] (zero rows for n >= N). grid (Npad/32, K/32), block (32,8)
__global__ void transpose_split(const float* __restrict__ W,
                                __nv_bfloat16* __restrict__ Bh,
                                __nv_bfloat16* __restrict__ Bl,
                                int K, int N)
{
    __shared__ float t[32][33];
    int n0 = blockIdx.x * 32, k0 = blockIdx.y * 32;
    int x = threadIdx.x, y = threadIdx.y;
    #pragma unroll
    for (int j = 0; j < 32; j += 8) {
        int k = k0 + y + j, n = n0 + x;
        t[y + j][x] = (n < N) ? W[(size_t)k * N + n] : 0.f;
    }
    __syncthreads();
    #pragma unroll
    for (int j = 0; j < 32; j += 8) {
        int n = n0 + y + j, k = k0 + x;
        float v = t[x][y + j];
        __nv_bfloat16 h = __float2bfloat16(v);
        Bh[(size_t)n * K + k] = h;
        Bl[(size_t)n * K + k] = __float2bfloat16(v - __bfloat162float(h));
    }
}

// ---------------------------------------------------------------------------
// Split-bf16 GEMM via mma.sync (unchanged from R6: 4-stage ring, BK=16)
// ---------------------------------------------------------------------------
#define GS_A_LO  6144
#define GS_B_HI  12288
#define GS_B_LO  18432
#define GS_STAGE 24576

__global__ __launch_bounds__(256) void gemm_mma(
    const __nv_bfloat16* __restrict__ Ah, const __nv_bfloat16* __restrict__ Al,
    const __nv_bfloat16* __restrict__ Bh, const __nv_bfloat16* __restrict__ Bl,
    const float* __restrict__ bias, float* __restrict__ C,
    int K, int Nreal, int ldC)
{
    extern __shared__ char smem[];
    const uint32_t sb = smem_to_u32(smem);
    const int tid = threadIdx.x, warp = tid >> 5, lane = tid & 31;
    const int n0 = blockIdx.x * 128, m0 = blockIdx.y * 128;
    const int warpM = warp >> 2, warpN = warp & 3;      // 2 x 4
    const int S = K >> 4;                                // BK = 16

    float d[4][4][4];
    #pragma unroll
    for (int mt = 0; mt < 4; mt++)
        #pragma unroll
        for (int nt = 0; nt < 4; nt++)
            #pragma unroll
            for (int e = 0; e < 4; e++) d[mt][nt][e] = 0.f;

    const int lrow = tid >> 1, lc = tid & 1;
    auto load_stage = [&](int s, int buf) {
        const size_t kc = ((size_t)s << 4) + lc * 8;
        uint32_t so = (uint32_t)buf * GS_STAGE + lrow * 48 + lc * 16;
        size_t ga = (size_t)(m0 + lrow) * K + kc;
        size_t gb = (size_t)(n0 + lrow) * K + kc;
        cp_async16(sb + so,           Ah + ga);
        cp_async16(sb + so + GS_A_LO, Al + ga);
        cp_async16(sb + so + GS_B_HI, Bh + gb);
        cp_async16(sb + so + GS_B_LO, Bl + gb);
        CP_COMMIT();
    };

    load_stage(0, 0);
    load_stage(1, 1);
    load_stage(2, 2);

    const uint32_t off = (uint32_t)(lane & 15) * 48 + (uint32_t)(lane >> 4) * 16;

    for (int s = 0; s < S; s++) {
        if (s <= S - 3)      CP_WAIT(2);
        else if (s == S - 2) CP_WAIT(1);
        else                 CP_WAIT(0);
        __syncthreads();
        if (s + 3 < S) load_stage(s + 3, (s + 3) & 3);

        const uint32_t base  = sb + (uint32_t)(s & 3) * GS_STAGE;
        const uint32_t aBase = base + (uint32_t)(warpM * 64) * 48;
        const uint32_t bBase = base + GS_B_HI + (uint32_t)(warpN * 32) * 48;

        uint32_t aH[4][4], aL[4][4], bH[2][4], bL[2][4];
        #pragma unroll
        for (int mt = 0; mt < 4; mt++) {
            uint32_t ad = aBase + (uint32_t)(mt * 16) * 48 + off;
            ldm_x4(aH[mt], ad);
            ldm_x4(aL[mt], ad + GS_A_LO);
        }
        #pragma unroll
        for (int ng = 0; ng < 2; ng++) {
            uint32_t bd = bBase + (uint32_t)(ng * 16) * 48 + off;
            ldm_x4(bH[ng], bd);
            ldm_x4(bL[ng], bd + (GS_B_LO - GS_B_HI));
        }
        #pragma unroll
        for (int mt = 0; mt < 4; mt++)
            #pragma unroll
            for (int ng = 0; ng < 2; ng++) {
                mma_bf16(d[mt][2 * ng],     aH[mt], bH[ng][0], bH[ng][2]);
                mma_bf16(d[mt][2 * ng + 1], aH[mt], bH[ng][1], bH[ng][3]);
                mma_bf16(d[mt][2 * ng],     aH[mt], bL[ng][0], bL[ng][2]);
                mma_bf16(d[mt][2 * ng + 1], aH[mt], bL[ng][1], bL[ng][3]);
                mma_bf16(d[mt][2 * ng],     aL[mt], bH[ng][0], bH[ng][2]);
                mma_bf16(d[mt][2 * ng + 1], aL[mt], bH[ng][1], bH[ng][3]);
            }
    }

    const int r0 = m0 + warpM * 64 + (lane >> 2);
    const int c0 = n0 + warpN * 32 + (lane & 3) * 2;
    #pragma unroll
    for (int mt = 0; mt < 4; mt++) {
        #pragma unroll
        for (int nt = 0; nt < 4; nt++) {
            int cc = c0 + nt * 8;
            float* p0 = C + (size_t)(r0 + mt * 16) * ldC;
            float* p1 = p0 + 8 * (size_t)ldC;
            if (cc < Nreal) {
                float bv = bias ? bias[cc] : 0.f;
                p0[cc] = d[mt][nt][0] + bv;
                p1[cc] = d[mt][nt][2] + bv;
            }
            if (cc + 1 < Nreal) {
                float bv = bias ? bias[cc + 1] : 0.f;
                p0[cc + 1] = d[mt][nt][1] + bv;
                p1[cc + 1] = d[mt][nt][3] + bv;
            }
        }
    }
}

// ---------------------------------------------------------------------------
// SRU scan: 16384 recurrences, 8-deep register prefetch; grid 128x128 so
// all SMs participate (was 64 CTAs -> half the chip idle).
// ---------------------------------------------------------------------------
__global__ void sru_scan(
    const float* __restrict__ U, const float* __restrict__ res,
    const float* __restrict__ vc, const float* __restrict__ bias,
    float* __restrict__ out, int L, int Bb, int H, int k)
{
    int idx = blockIdx.x * blockDim.x + threadIdx.x;
    if (idx >= Bb * H) return;
    int hh = idx % H, b = idx / H;
    float vf = vc[hh], vr = vc[H + hh];
    float bf = bias[hh], br = bias[H + hh];
    float c = 0.f;

    size_t ustep = (size_t)Bb * k * H;
    size_t ubase = (size_t)b * k * H + hh;
    size_t ostep = (size_t)Bb * H;
    size_t obase = (size_t)b * H + hh;

    const float* u  = U + ubase;
    const float* rp = (k == 3) ? (res + obase) : (U + ubase + 3 * (size_t)H);
    size_t rstep    = (k == 3) ? ostep : ustep;
    float* o = out + obase;

    float pa0[8], pa1[8], pa2[8], prt[8];
    #pragma unroll
    for (int j = 0; j < 8; j++) {
        size_t uo = (size_t)j * ustep;
        pa0[j] = __ldcs(u + uo);
        pa1[j] = __ldcs(u + uo + H);
        pa2[j] = __ldcs(u + uo + 2 * (size_t)H);
        prt[j] = __ldcs(rp + (size_t)j * rstep);
    }

    #pragma unroll 8
    for (int t = 0; t < L; ++t) {
        int j = t & 7;
        float a0 = pa0[j], a1 = pa1[j], a2 = pa2[j], rt = prt[j];
        int tn = (t + 8 < L) ? (t + 8) : (L - 1);
        size_t uo = (size_t)tn * ustep;
        pa0[j] = __ldcs(u + uo);
        pa1[j] = __ldcs(u + uo + H);
        pa2[j] = __ldcs(u + uo + 2 * (size_t)H);
        prt[j] = __ldcs(rp + (size_t)tn * rstep);

        float f = sigf(a1 + vf * c + bf);
        float r = sigf(a2 + vr * c + br);
        c = f * c + (1.f - f) * a0;
        o[(size_t)t * ostep] = r * c + (1.f - r) * rt;
    }
}

__global__ void pool2(const float* __restrict__ in, float* __restrict__ out, int n)
{
    int i = blockIdx.x * blockDim.x + threadIdx.x;
    if (i >= n) return;
    int lp = i >> 14;
    size_t j = (size_t)i + (size_t)lp * 16384;
    out[i] = 0.5f * (in[j] + in[j + 16384]);
}

__global__ void addvec(const float* __restrict__ a, const float* __restrict__ b,
                       float* __restrict__ o, int n)
{
    int i = blockIdx.x * blockDim.x + threadIdx.x;
    if (i < n) o[i] = a[i] + b[i];
}

__global__ void lstm_init(float* h0)
{
    int i = blockIdx.x * blockDim.x + threadIdx.x;
    if (i < 16384) h0[i] = 0.f;
    if (i == 0) { g_bar_count = 0u; g_bar_gen = 0u; }
}

// ---------------------------------------------------------------------------
// Persistent LSTM (148 CTAs, grid barrier per step). Inner dot products use
// packed fma.rn.f32x2 over adjacent K pairs -> 2x fma-pipe throughput.
// ---------------------------------------------------------------------------
__global__ __launch_bounds__(256) void lstm_persist(
    const float* __restrict__ pre, const float* __restrict__ Whh,
    float* __restrict__ hbuf0, float* __restrict__ hbuf1,
    float* __restrict__ hout)
{
    extern __shared__ float hs[];
    float4* hs4 = (float4*)hs;
    const ulonglong2* hs2 = (const ulonglong2*)hs;
    const int tid = threadIdx.x, bid = blockIdx.x;
    const int warp = tid >> 5, lane = tid & 31;

    int cnt, s;
    if (bid < 136) { cnt = 7; s = bid * 7; }
    else           { cnt = 6; s = 952 + (bid - 136) * 6; }
    const bool active = warp < cnt;
    const int hh = s + (active ? warp : 0);

    const ulonglong2* W2[4];
    #pragma unroll
    for (int g = 0; g < 4; g++)
        W2[g] = (const ulonglong2*)(Whh + ((size_t)g * 1024 + hh) * 1024);

    float c = 0.f;

    for (int t = 0; t < 512; t++) {
        const float4* hsrc = (const float4*)((t & 1) ? hbuf1 : hbuf0);
        float*        hdst = (t & 1) ? hbuf0 : hbuf1;

        __syncthreads();
        for (int i = tid; i < 4096; i += 256) hs4[i] = __ldcg(hsrc + i);
        __syncthreads();

        if (active) {
            unsigned long long acc2[4][16];
            #pragma unroll
            for (int g = 0; g < 4; g++)
                #pragma unroll
                for (int b = 0; b < 16; b++) acc2[g][b] = 0ull;

            #pragma unroll 1
            for (int i = lane; i < 256; i += 32) {
                ulonglong2 wq[4];
                #pragma unroll
                for (int g = 0; g < 4; g++) wq[g] = W2[g][i];
                #pragma unroll
                for (int b = 0; b < 16; b++) {
                    ulonglong2 hq = hs2[b * 256 + i];
                    #pragma unroll
                    for (int g = 0; g < 4; g++) {
                        fma_f32x2(acc2[g][b], wq[g].x, hq.x);
                        fma_f32x2(acc2[g][b], wq[g].y, hq.y);
                    }
                }
            }

            float gate[4] = {0.f, 0.f, 0.f, 0.f};
            #pragma unroll
            for (int g = 0; g < 4; g++)
                #pragma unroll
                for (int b = 0; b < 16; b++) {
                    F2U u2; u2.u = acc2[g][b];
                    float v = u2.f.x + u2.f.y;
                    #pragma unroll
                    for (int o = 16; o; o >>= 1)
                        v += __shfl_xor_sync(0xffffffffu, v, o);
                    if (lane == b) gate[g] = v;
                }

            if (lane < 16) {
                const float* pb = pre + (size_t)t * 65536 + (size_t)lane * 4096;
                float ig = sigf(gate[0] + pb[hh]);
                float fg = sigf(gate[1] + pb[1024 + hh]);
                float gg = tanhf(gate[2] + pb[2048 + hh]);
                float og = sigf(gate[3] + pb[3072 + hh]);
                c = fg * c + ig * gg;
                float hv = og * tanhf(c);
                hdst[lane * 1024 + hh] = hv;
                hout[(size_t)t * 16384 + lane * 1024 + hh] = hv;
            }
        }

        __syncthreads();
        if (tid == 0) {
            __threadfence();
            unsigned prev = atomicAdd(&g_bar_count, 1u);
            if (prev == 147u) {
                atomicExch(&g_bar_count, 0u);
                __threadfence();
                atomicExch(&g_bar_gen, (unsigned)(t + 1));
            } else {
                while (*(volatile unsigned*)&g_bar_gen < (unsigned)(t + 1))
                    __nanosleep(32);
            }
            __threadfence();
        }
    }
}

// ---------------------------------------------------------------------------
// Orchestration
// ---------------------------------------------------------------------------
extern "C" void kernel_launch(void* const* d_in, const int* in_sizes, int n_in,
                              void* d_out, int out_size)
{
    const float* x    = (const float*)d_in[0];
    const float* w0   = (const float*)d_in[1];
    const float* vc0  = (const float*)d_in[2];
    const float* b0   = (const float*)d_in[3];
    const float* g0   = (const float*)d_in[4];
    const float* be0  = (const float*)d_in[5];
    const float* Ws   = (const float*)d_in[6];
    const float* VCs  = (const float*)d_in[7];
    const float* Bsb  = (const float*)d_in[8];
    const float* Gs   = (const float*)d_in[9];
    const float* Bes  = (const float*)d_in[10];
    const float* Wih  = (const float*)d_in[11];
    const float* Whh  = (const float*)d_in[12];
    const float* bih  = (const float*)d_in[13];
    const float* bhh  = (const float*)d_in[14];
    const float* gh   = (const float*)d_in[15];
    const float* bhv  = (const float*)d_in[16];
    const float* Wout = (const float*)d_in[17];
    float* out = (float*)d_out;

    float *xn, *U, *hA, *hB, *bsum, *h0, *h1;
    __nv_bfloat16 *Ah, *Al, *Bh, *Bl;
    cudaGetSymbolAddress((void**)&xn,   g_xn);
    cudaGetSymbolAddress((void**)&U,    g_U);
    cudaGetSymbolAddress((void**)&hA,   g_hA);
    cudaGetSymbolAddress((void**)&hB,   g_hB);
    cudaGetSymbolAddress((void**)&bsum, g_bsum);
    cudaGetSymbolAddress((void**)&h0,   g_h0);
    cudaGetSymbolAddress((void**)&h1,   g_h1);
    cudaGetSymbolAddress((void**)&Ah,   g_Ah);
    cudaGetSymbolAddress((void**)&Al,   g_Al);
    cudaGetSymbolAddress((void**)&Bh,   g_Bh);
    cudaGetSymbolAddress((void**)&Bl,   g_Bl);

    cudaFuncSetAttribute(lstm_persist, cudaFuncAttributeMaxDynamicSharedMemorySize, 65536);
    cudaFuncSetAttribute(gemm_mma,    cudaFuncAttributeMaxDynamicSharedMemorySize, 4 * GS_STAGE);

    const int B = 16, H = 1024;
    const int GSM = 4 * GS_STAGE;

    // ---- SRU layer 0: (B,1024,128) -> (1024,B,1024) ----
    ln_rows<<<16384, 256>>>(x, xn, Ah, Al, g0, be0, 1024, B, 128, 1, 0);
    { dim3 g(4096 / 32, 128 / 32); dim3 bl(32, 8);
      transpose_split<<<g, bl>>>(w0, Bh, Bl, 128, 4096); }
    { dim3 g(32, 128); gemm_mma<<<g, 256, GSM>>>(Ah, Al, Bh, Bl, nullptr, U, 128, 4096, 4096); }
    sru_scan<<<128, 128>>>(U, nullptr, vc0, b0, hA, 1024, B, H, 4);

    float* cur = hA; float* alt = hB;

    // ---- SRU layers 1-3 (L=1024) ----
    for (int i = 0; i < 3; i++) {
        ln_rows<<<16384, 256>>>(cur, xn, Ah, Al, Gs + i * H, Bes + i * H, 1024, B, H, 0, 0);
        { dim3 g(3072 / 32, 1024 / 32); dim3 bl(32, 8);
          transpose_split<<<g, bl>>>(Ws + (size_t)i * H * 3072, Bh, Bl, 1024, 3072); }
        { dim3 g(24, 128); gemm_mma<<<g, 256, GSM>>>(Ah, Al, Bh, Bl, nullptr, U, 1024, 3072, 3072); }
        sru_scan<<<128, 128>>>(U, xn, VCs + i * 2048, Bsb + i * 2048, alt, 1024, B, H, 3);
        float* t2 = cur; cur = alt; alt = t2;
    }

    // ---- time pooling 1024 -> 512 ----
    pool2<<<32768, 256>>>(cur, alt, 512 * 16 * 1024);
    { float* t2 = cur; cur = alt; alt = t2; }

    // ---- SRU layers 4-6 (L=512) ----
    for (int i = 3; i < 6; i++) {
        ln_rows<<<8192, 256>>>(cur, xn, Ah, Al, Gs + i * H, Bes + i * H, 512, B, H, 0, 0);
        { dim3 g(3072 / 32, 1024 / 32); dim3 bl(32, 8);
          transpose_split<<<g, bl>>>(Ws + (size_t)i * H * 3072, Bh, Bl, 1024, 3072); }
        { dim3 g(24, 64); gemm_mma<<<g, 256, GSM>>>(Ah, Al, Bh, Bl, nullptr, U, 1024, 3072, 3072); }
        sru_scan<<<128, 128>>>(U, xn, VCs + i * 2048, Bsb + i * 2048, alt, 512, B, H, 3);
        float* t2 = cur; cur = alt; alt = t2;
    }

    // ---- LSTM: pre-GEMM (Wih already [4096,1024] = B layout) ----
    addvec<<<16, 256>>>(bih, bhh, bsum, 4096);
    conv_split<<<32768, 256>>>(cur, Ah, Al, 8192 * 1024);
    conv_split<<<16384, 256>>>(Wih, Bh, Bl, 4096 * 1024);
    { dim3 g(32, 64); gemm_mma<<<g, 256, GSM>>>(Ah, Al, Bh, Bl, bsum, U, 1024, 4096, 4096); }
    lstm_init<<<64, 256>>>(h0);
    lstm_persist<<<148, 256, 65536>>>(U, Whh, h0, h1, alt);

    // ---- final LN (written (b,l)-major) + projection to (16,512,1001) ----
    ln_rows<<<8192, 256>>>(alt, xn, Ah, Al, gh, bhv, 512, B, H, 0, 1);
    { dim3 g(1024 / 32, 1024 / 32); dim3 bl(32, 8);
      transpose_split<<<g, bl>>>(Wout, Bh, Bl, 1024, 1001); }
    { dim3 g(8, 64); gemm_mma<<<g, 256, GSM>>>(Ah, Al, Bh, Bl, nullptr, out, 1024, 1001, 1001); }
}

// round 10
// speedup vs baseline: 1.9843x; 1.0439x over previous
#include <cuda_runtime.h>
#include <cuda_bf16.h>
#include <cstdint>
#include <cstddef>

// ---------------------------------------------------------------------------
// Scratch (device globals; no allocation allowed anywhere)
// ---------------------------------------------------------------------------
__device__ float g_xn [16777216];   // max 16384 rows x 1024
__device__ float g_U  [67108864];   // 1024*16*4096
__device__ float g_hA [16777216];
__device__ float g_hB [16777216];
__device__ float g_bsum[4096];
__device__ float g_h0 [16384];
__device__ float g_h1 [16384];
__device__ unsigned g_bar_count;
__device__ unsigned g_bar_gen;
__device__ __nv_bfloat16 g_Ah[16777216];  // activation hi split
__device__ __nv_bfloat16 g_Al[16777216];  // activation lo split
__device__ __nv_bfloat16 g_Bh[4194304];   // weight hi split [Npad][K]
__device__ __nv_bfloat16 g_Bl[4194304];   // weight lo split

#define LN_EPS 1e-5f

__device__ __forceinline__ float sigf(float x) {
    return __fdividef(1.f, 1.f + __expf(-x));
}

__device__ __forceinline__ uint32_t smem_to_u32(const void* p) {
    uint32_t a;
    asm("{ .reg .u64 t; cvta.to.shared.u64 t, %1; cvt.u32.u64 %0, t; }"
        : "=r"(a) : "l"(p));
    return a;
}

// packed f32x2 fma: acc(lo,hi) += a(lo,hi) * b(lo,hi)
__device__ __forceinline__ void fma_f32x2(unsigned long long& acc,
                                          unsigned long long a,
                                          unsigned long long b) {
    asm("fma.rn.f32x2 %0, %1, %2, %0;" : "+l"(acc) : "l"(a), "l"(b));
}
union F2U { unsigned long long u; float2 f; };

// ---------------------------------------------------------------------------
// mma.sync / ldmatrix / cp.async primitives (base sm_103 target)
// ---------------------------------------------------------------------------
__device__ __forceinline__ void ldm_x4(uint32_t* r, uint32_t addr) {
    asm volatile("ldmatrix.sync.aligned.m8n8.x4.shared.b16 {%0,%1,%2,%3}, [%4];"
                 : "=r"(r[0]), "=r"(r[1]), "=r"(r[2]), "=r"(r[3]) : "r"(addr));
}
__device__ __forceinline__ void mma_bf16(float* d, const uint32_t* a,
                                         uint32_t b0, uint32_t b1) {
    asm volatile(
        "mma.sync.aligned.m16n8k16.row.col.f32.bf16.bf16.f32 "
        "{%0,%1,%2,%3}, {%4,%5,%6,%7}, {%8,%9}, {%0,%1,%2,%3};"
        : "+f"(d[0]), "+f"(d[1]), "+f"(d[2]), "+f"(d[3])
        : "r"(a[0]), "r"(a[1]), "r"(a[2]), "r"(a[3]), "r"(b0), "r"(b1));
}
__device__ __forceinline__ void cp_async16(uint32_t saddr, const void* gptr) {
    asm volatile("cp.async.cg.shared.global [%0], [%1], 16;"
                 :: "r"(saddr), "l"(__cvta_generic_to_global(gptr)));
}
#define CP_COMMIT()  asm volatile("cp.async.commit_group;" ::: "memory")
#define CP_WAIT(n)   asm volatile("cp.async.wait_group %0;" :: "n"(n) : "memory")

// ---------------------------------------------------------------------------
// Block reduction helper (256-thread blocks)
// ---------------------------------------------------------------------------
__device__ __forceinline__ float blockReduceSum(float v, float* shm) {
    int lane = threadIdx.x & 31, wid = threadIdx.x >> 5;
    #pragma unroll
    for (int o = 16; o; o >>= 1) v += __shfl_xor_sync(0xffffffffu, v, o);
    if (lane == 0) shm[wid] = v;
    __syncthreads();
    int nw = (blockDim.x + 31) >> 5;
    float r = (threadIdx.x < nw) ? shm[threadIdx.x] : 0.f;
    if (wid == 0) {
        #pragma unroll
        for (int o = 16; o; o >>= 1) r += __shfl_xor_sync(0xffffffffu, r, o);
        if (lane == 0) shm[0] = r;
    }
    __syncthreads();
    float total = shm[0];
    __syncthreads();
    return total;
}

// ---------------------------------------------------------------------------
// LayerNorm over last dim, fused bf16 hi/lo split output (hi/lo nullable).
// ---------------------------------------------------------------------------
__global__ __launch_bounds__(256) void ln_rows(
    const float* __restrict__ src, float* __restrict__ dst,
    __nv_bfloat16* __restrict__ hi, __nv_bfloat16* __restrict__ lo,
    const float* __restrict__ g, const float* __restrict__ be,
    int L, int Bb, int D, int srcBMajor, int dstBMajor)
{
    __shared__ float shm[32];
    int r = blockIdx.x;
    int l = r / Bb, b = r % Bb;
    const float* s = src + (srcBMajor ? ((size_t)b * L + l) : (size_t)r) * D;
    size_t drow = (dstBMajor ? ((size_t)b * L + l) : (size_t)r) * D;
    float* d = dst + drow;

    float sum = 0.f;
    for (int i = 4 * threadIdx.x; i < D; i += 1024) {
        float4 v = *(const float4*)(s + i);
        sum += (v.x + v.y) + (v.z + v.w);
    }
    float mean = blockReduceSum(sum, shm) / (float)D;

    float vs = 0.f;
    for (int i = 4 * threadIdx.x; i < D; i += 1024) {
        float4 v = *(const float4*)(s + i);
        float a = v.x - mean, bq = v.y - mean, c = v.z - mean, e = v.w - mean;
        vs += a * a + bq * bq + c * c + e * e;
    }
    float var = blockReduceSum(vs, shm) / (float)D;
    float rstd = rsqrtf(var + LN_EPS);

    for (int i = 4 * threadIdx.x; i < D; i += 1024) {
        float4 v = *(const float4*)(s + i);
        float4 gv = *(const float4*)(g + i);
        float4 bv = *(const float4*)(be + i);
        float4 o;
        o.x = (v.x - mean) * rstd * gv.x + bv.x;
        o.y = (v.y - mean) * rstd * gv.y + bv.y;
        o.z = (v.z - mean) * rstd * gv.z + bv.z;
        o.w = (v.w - mean) * rstd * gv.w + bv.w;
        *(float4*)(d + i) = o;
        if (hi) {
            __nv_bfloat16 h0v = __float2bfloat16(o.x);
            __nv_bfloat16 h1v = __float2bfloat16(o.y);
            __nv_bfloat16 h2v = __float2bfloat16(o.z);
            __nv_bfloat16 h3v = __float2bfloat16(o.w);
            __nv_bfloat162* hp = (__nv_bfloat162*)(hi + drow + i);
            __nv_bfloat162* lp = (__nv_bfloat162*)(lo + drow + i);
            hp[0] = __nv_bfloat162(h0v, h1v);
            hp[1] = __nv_bfloat162(h2v, h3v);
            lp[0] = __nv_bfloat162(
                __float2bfloat16(o.x - __bfloat162float(h0v)),
                __float2bfloat16(o.y - __bfloat162float(h1v)));
            lp[1] = __nv_bfloat162(
                __float2bfloat16(o.z - __bfloat162float(h2v)),
                __float2bfloat16(o.w - __bfloat162float(h3v)));
        }
    }
}

// ---------------------------------------------------------------------------
// Split conversion: fp32 -> (bf16 hi, bf16 lo)
// ---------------------------------------------------------------------------
__global__ void conv_split(const float* __restrict__ x,
                           __nv_bfloat16* __restrict__ hi,
                           __nv_bfloat16* __restrict__ lo, int n)
{
    int i = blockIdx.x * blockDim.x + threadIdx.x;
    if (i >= n) return;
    float v = x[i];
    __nv_bfloat16 h = __float2bfloat16(v);
    hi[i] = h;
    lo[i] = __float2bfloat16(v - __bfloat162float(h));
}

// W[K][N] -> Bh/Bl [Npad][K] (zero rows for n >= N). grid (Npad/32, K/32), block (32,8)
__global__ void transpose_split(const float* __restrict__ W,
                                __nv_bfloat16* __restrict__ Bh,
                                __nv_bfloat16* __restrict__ Bl,
                                int K, int N)
{
    __shared__ float t[32][33];
    int n0 = blockIdx.x * 32, k0 = blockIdx.y * 32;
    int x = threadIdx.x, y = threadIdx.y;
    #pragma unroll
    for (int j = 0; j < 32; j += 8) {
        int k = k0 + y + j, n = n0 + x;
        t[y + j][x] = (n < N) ? W[(size_t)k * N + n] : 0.f;
    }
    __syncthreads();
    #pragma unroll
    for (int j = 0; j < 32; j += 8) {
        int n = n0 + y + j, k = k0 + x;
        float v = t[x][y + j];
        __nv_bfloat16 h = __float2bfloat16(v);
        Bh[(size_t)n * K + k] = h;
        Bl[(size_t)n * K + k] = __float2bfloat16(v - __bfloat162float(h));
    }
}

// ---------------------------------------------------------------------------
// Split-bf16 GEMM via mma.sync (4-stage ring, BK=16). Epilogue: float2
// stores ONLY when ldC is even (odd ldC breaks 8B alignment -> trap).
// ---------------------------------------------------------------------------
#define GS_A_LO  6144
#define GS_B_HI  12288
#define GS_B_LO  18432
#define GS_STAGE 24576

__global__ __launch_bounds__(256) void gemm_mma(
    const __nv_bfloat16* __restrict__ Ah, const __nv_bfloat16* __restrict__ Al,
    const __nv_bfloat16* __restrict__ Bh, const __nv_bfloat16* __restrict__ Bl,
    const float* __restrict__ bias, float* __restrict__ C,
    int K, int Nreal, int ldC)
{
    extern __shared__ char smem[];
    const uint32_t sb = smem_to_u32(smem);
    const int tid = threadIdx.x, warp = tid >> 5, lane = tid & 31;
    const int n0 = blockIdx.x * 128, m0 = blockIdx.y * 128;
    const int warpM = warp >> 2, warpN = warp & 3;      // 2 x 4
    const int S = K >> 4;                                // BK = 16

    float d[4][4][4];
    #pragma unroll
    for (int mt = 0; mt < 4; mt++)
        #pragma unroll
        for (int nt = 0; nt < 4; nt++)
            #pragma unroll
            for (int e = 0; e < 4; e++) d[mt][nt][e] = 0.f;

    const int lrow = tid >> 1, lc = tid & 1;
    auto load_stage = [&](int s, int buf) {
        const size_t kc = ((size_t)s << 4) + lc * 8;
        uint32_t so = (uint32_t)buf * GS_STAGE + lrow * 48 + lc * 16;
        size_t ga = (size_t)(m0 + lrow) * K + kc;
        size_t gb = (size_t)(n0 + lrow) * K + kc;
        cp_async16(sb + so,           Ah + ga);
        cp_async16(sb + so + GS_A_LO, Al + ga);
        cp_async16(sb + so + GS_B_HI, Bh + gb);
        cp_async16(sb + so + GS_B_LO, Bl + gb);
        CP_COMMIT();
    };

    load_stage(0, 0);
    load_stage(1, 1);
    load_stage(2, 2);

    const uint32_t off = (uint32_t)(lane & 15) * 48 + (uint32_t)(lane >> 4) * 16;

    for (int s = 0; s < S; s++) {
        if (s <= S - 3)      CP_WAIT(2);
        else if (s == S - 2) CP_WAIT(1);
        else                 CP_WAIT(0);
        __syncthreads();
        if (s + 3 < S) load_stage(s + 3, (s + 3) & 3);

        const uint32_t base  = sb + (uint32_t)(s & 3) * GS_STAGE;
        const uint32_t aBase = base + (uint32_t)(warpM * 64) * 48;
        const uint32_t bBase = base + GS_B_HI + (uint32_t)(warpN * 32) * 48;

        uint32_t aH[4][4], aL[4][4], bH[2][4], bL[2][4];
        #pragma unroll
        for (int mt = 0; mt < 4; mt++) {
            uint32_t ad = aBase + (uint32_t)(mt * 16) * 48 + off;
            ldm_x4(aH[mt], ad);
            ldm_x4(aL[mt], ad + GS_A_LO);
        }
        #pragma unroll
        for (int ng = 0; ng < 2; ng++) {
            uint32_t bd = bBase + (uint32_t)(ng * 16) * 48 + off;
            ldm_x4(bH[ng], bd);
            ldm_x4(bL[ng], bd + (GS_B_LO - GS_B_HI));
        }
        #pragma unroll
        for (int mt = 0; mt < 4; mt++)
            #pragma unroll
            for (int ng = 0; ng < 2; ng++) {
                mma_bf16(d[mt][2 * ng],     aH[mt], bH[ng][0], bH[ng][2]);
                mma_bf16(d[mt][2 * ng + 1], aH[mt], bH[ng][1], bH[ng][3]);
                mma_bf16(d[mt][2 * ng],     aH[mt], bL[ng][0], bL[ng][2]);
                mma_bf16(d[mt][2 * ng + 1], aH[mt], bL[ng][1], bL[ng][3]);
                mma_bf16(d[mt][2 * ng],     aL[mt], bH[ng][0], bH[ng][2]);
                mma_bf16(d[mt][2 * ng + 1], aL[mt], bH[ng][1], bH[ng][3]);
            }
    }

    const int r0 = m0 + warpM * 64 + (lane >> 2);
    const int c0 = n0 + warpN * 32 + (lane & 3) * 2;
    const bool vec = ((ldC & 1) == 0);
    #pragma unroll
    for (int mt = 0; mt < 4; mt++) {
        #pragma unroll
        for (int nt = 0; nt < 4; nt++) {
            int cc = c0 + nt * 8;
            float* p0 = C + (size_t)(r0 + mt * 16) * ldC;
            float* p1 = p0 + 8 * (size_t)ldC;
            if (vec && cc + 1 < Nreal) {
                float b0v = bias ? bias[cc] : 0.f;
                float b1v = bias ? bias[cc + 1] : 0.f;
                *(float2*)(p0 + cc) = make_float2(d[mt][nt][0] + b0v, d[mt][nt][1] + b1v);
                *(float2*)(p1 + cc) = make_float2(d[mt][nt][2] + b0v, d[mt][nt][3] + b1v);
            } else {
                if (cc < Nreal) {
                    float bv = bias ? bias[cc] : 0.f;
                    p0[cc] = d[mt][nt][0] + bv;
                    p1[cc] = d[mt][nt][2] + bv;
                }
                if (cc + 1 < Nreal) {
                    float bv = bias ? bias[cc + 1] : 0.f;
                    p0[cc + 1] = d[mt][nt][1] + bv;
                    p1[cc + 1] = d[mt][nt][3] + bv;
                }
            }
        }
    }
}

// ---------------------------------------------------------------------------
// SRU scan: 16384 recurrences; 16-deep register prefetch ring (64 LDG in
// flight per warp ~ M_max), grid 256 x 64 covers every SM.
// ---------------------------------------------------------------------------
__global__ void sru_scan(
    const float* __restrict__ U, const float* __restrict__ res,
    const float* __restrict__ vc, const float* __restrict__ bias,
    float* __restrict__ out, int L, int Bb, int H, int k)
{
    int idx = blockIdx.x * blockDim.x + threadIdx.x;
    if (idx >= Bb * H) return;
    int hh = idx % H, b = idx / H;
    float vf = vc[hh], vr = vc[H + hh];
    float bf = bias[hh], br = bias[H + hh];
    float c = 0.f;

    size_t ustep = (size_t)Bb * k * H;
    size_t ubase = (size_t)b * k * H + hh;
    size_t ostep = (size_t)Bb * H;
    size_t obase = (size_t)b * H + hh;

    const float* u  = U + ubase;
    const float* rp = (k == 3) ? (res + obase) : (U + ubase + 3 * (size_t)H);
    size_t rstep    = (k == 3) ? ostep : ustep;
    float* o = out + obase;

    float pa0[16], pa1[16], pa2[16], prt[16];
    #pragma unroll
    for (int j = 0; j < 16; j++) {
        size_t uo = (size_t)j * ustep;
        pa0[j] = __ldcs(u + uo);
        pa1[j] = __ldcs(u + uo + H);
        pa2[j] = __ldcs(u + uo + 2 * (size_t)H);
        prt[j] = __ldcs(rp + (size_t)j * rstep);
    }

    #pragma unroll 16
    for (int t = 0; t < L; ++t) {
        int j = t & 15;
        float a0 = pa0[j], a1 = pa1[j], a2 = pa2[j], rt = prt[j];
        int tn = (t + 16 < L) ? (t + 16) : (L - 1);
        size_t uo = (size_t)tn * ustep;
        pa0[j] = __ldcs(u + uo);
        pa1[j] = __ldcs(u + uo + H);
        pa2[j] = __ldcs(u + uo + 2 * (size_t)H);
        prt[j] = __ldcs(rp + (size_t)tn * rstep);

        float f = sigf(a1 + vf * c + bf);
        float r = sigf(a2 + vr * c + br);
        c = f * c + (1.f - f) * a0;
        o[(size_t)t * ostep] = r * c + (1.f - r) * rt;
    }
}

__global__ void pool2(const float* __restrict__ in, float* __restrict__ out, int n)
{
    int i = blockIdx.x * blockDim.x + threadIdx.x;
    if (i >= n) return;
    int lp = i >> 14;
    size_t j = (size_t)i + (size_t)lp * 16384;
    out[i] = 0.5f * (in[j] + in[j + 16384]);
}

__global__ void addvec(const float* __restrict__ a, const float* __restrict__ b,
                       float* __restrict__ o, int n)
{
    int i = blockIdx.x * blockDim.x + threadIdx.x;
    if (i < n) o[i] = a[i] + b[i];
}

__global__ void lstm_init(float* h0)
{
    int i = blockIdx.x * blockDim.x + threadIdx.x;
    if (i < 16384) h0[i] = 0.f;
    if (i == 0) { g_bar_count = 0u; g_bar_gen = 0u; }
}

// ---------------------------------------------------------------------------
// Persistent LSTM (148 CTAs, grid barrier per step). f32x2 packed fma.
// h staged via cp.async in two K-halves; first half's dot products overlap
// the second half's in-flight copies. pre gate values prefetched early.
// ---------------------------------------------------------------------------
__global__ __launch_bounds__(256) void lstm_persist(
    const float* __restrict__ pre, const float* __restrict__ Whh,
    float* __restrict__ hbuf0, float* __restrict__ hbuf1,
    float* __restrict__ hout)
{
    extern __shared__ float hs[];    // 16 x 1024 floats = 64 KB
    const ulonglong2* hs2 = (const ulonglong2*)hs;
    const uint32_t hs_sb = smem_to_u32(hs);
    const int tid = threadIdx.x, bid = blockIdx.x;
    const int warp = tid >> 5, lane = tid & 31;

    int cnt, s;
    if (bid < 136) { cnt = 7; s = bid * 7; }
    else           { cnt = 6; s = 952 + (bid - 136) * 6; }
    const bool active = warp < cnt;
    const int hh = s + (active ? warp : 0);

    const ulonglong2* W2[4];
    #pragma unroll
    for (int g = 0; g < 4; g++)
        W2[g] = (const ulonglong2*)(Whh + ((size_t)g * 1024 + hh) * 1024);

    float c = 0.f;

    for (int t = 0; t < 512; t++) {
        const float* hsrc = (t & 1) ? hbuf1 : hbuf0;
        float*       hdst = (t & 1) ? hbuf0 : hbuf1;

        __syncthreads();

        // stage h: two 32 KB halves (split along K) via cp.async.cg
        #pragma unroll
        for (int half = 0; half < 2; half++) {
            #pragma unroll
            for (int j2 = 0; j2 < 8; j2++) {
                int cidx = tid + j2 * 256;           // 0..2047
                int b = cidx >> 7, kc = cidx & 127;
                uint32_t foff = (uint32_t)(b * 1024 + half * 512 + kc * 4);
                cp_async16(hs_sb + foff * 4, hsrc + foff);
            }
            CP_COMMIT();
        }

        // prefetch pre gate values (independent of h)
        float pv0 = 0.f, pv1 = 0.f, pv2 = 0.f, pv3 = 0.f;
        if (active && lane < 16) {
            const float* pb = pre + (size_t)t * 65536 + (size_t)lane * 4096;
            pv0 = __ldcg(pb + hh);
            pv1 = __ldcg(pb + 1024 + hh);
            pv2 = __ldcg(pb + 2048 + hh);
            pv3 = __ldcg(pb + 3072 + hh);
        }

        unsigned long long acc2[4][16];
        #pragma unroll
        for (int g = 0; g < 4; g++)
            #pragma unroll
            for (int b = 0; b < 16; b++) acc2[g][b] = 0ull;

        CP_WAIT(1);
        __syncthreads();     // half 1 (K 0..511) resident
        if (active) {
            #pragma unroll 1
            for (int i = lane; i < 128; i += 32) {
                ulonglong2 wq[4];
                #pragma unroll
                for (int g = 0; g < 4; g++) wq[g] = W2[g][i];
                #pragma unroll
                for (int b = 0; b < 16; b++) {
                    ulonglong2 hq = hs2[b * 256 + i];
                    #pragma unroll
                    for (int g = 0; g < 4; g++) {
                        fma_f32x2(acc2[g][b], wq[g].x, hq.x);
                        fma_f32x2(acc2[g][b], wq[g].y, hq.y);
                    }
                }
            }
        }
        CP_WAIT(0);
        __syncthreads();     // half 2 resident
        if (active) {
            #pragma unroll 1
            for (int i = 128 + lane; i < 256; i += 32) {
                ulonglong2 wq[4];
                #pragma unroll
                for (int g = 0; g < 4; g++) wq[g] = W2[g][i];
                #pragma unroll
                for (int b = 0; b < 16; b++) {
                    ulonglong2 hq = hs2[b * 256 + i];
                    #pragma unroll
                    for (int g = 0; g < 4; g++) {
                        fma_f32x2(acc2[g][b], wq[g].x, hq.x);
                        fma_f32x2(acc2[g][b], wq[g].y, hq.y);
                    }
                }
            }

            float gate[4] = {0.f, 0.f, 0.f, 0.f};
            #pragma unroll
            for (int g = 0; g < 4; g++)
                #pragma unroll
                for (int b = 0; b < 16; b++) {
                    F2U u2; u2.u = acc2[g][b];
                    float v = u2.f.x + u2.f.y;
                    #pragma unroll
                    for (int o = 16; o; o >>= 1)
                        v += __shfl_xor_sync(0xffffffffu, v, o);
                    if (lane == b) gate[g] = v;
                }

            if (lane < 16) {
                float ig = sigf(gate[0] + pv0);
                float fg = sigf(gate[1] + pv1);
                float gg = tanhf(gate[2] + pv2);
                float og = sigf(gate[3] + pv3);
                c = fg * c + ig * gg;
                float hv = og * tanhf(c);
                hdst[lane * 1024 + hh] = hv;
                hout[(size_t)t * 16384 + lane * 1024 + hh] = hv;
            }
        }

        __syncthreads();
        if (tid == 0) {
            __threadfence();
            unsigned prev = atomicAdd(&g_bar_count, 1u);
            if (prev == 147u) {
                atomicExch(&g_bar_count, 0u);
                __threadfence();
                atomicExch(&g_bar_gen, (unsigned)(t + 1));
            } else {
                while (*(volatile unsigned*)&g_bar_gen < (unsigned)(t + 1))
                    __nanosleep(32);
            }
            __threadfence();
        }
    }
}

// ---------------------------------------------------------------------------
// Orchestration
// ---------------------------------------------------------------------------
extern "C" void kernel_launch(void* const* d_in, const int* in_sizes, int n_in,
                              void* d_out, int out_size)
{
    const float* x    = (const float*)d_in[0];
    const float* w0   = (const float*)d_in[1];
    const float* vc0  = (const float*)d_in[2];
    const float* b0   = (const float*)d_in[3];
    const float* g0   = (const float*)d_in[4];
    const float* be0  = (const float*)d_in[5];
    const float* Ws   = (const float*)d_in[6];
    const float* VCs  = (const float*)d_in[7];
    const float* Bsb  = (const float*)d_in[8];
    const float* Gs   = (const float*)d_in[9];
    const float* Bes  = (const float*)d_in[10];
    const float* Wih  = (const float*)d_in[11];
    const float* Whh  = (const float*)d_in[12];
    const float* bih  = (const float*)d_in[13];
    const float* bhh  = (const float*)d_in[14];
    const float* gh   = (const float*)d_in[15];
    const float* bhv  = (const float*)d_in[16];
    const float* Wout = (const float*)d_in[17];
    float* out = (float*)d_out;

    float *xn, *U, *hA, *hB, *bsum, *h0, *h1;
    __nv_bfloat16 *Ah, *Al, *Bh, *Bl;
    cudaGetSymbolAddress((void**)&xn,   g_xn);
    cudaGetSymbolAddress((void**)&U,    g_U);
    cudaGetSymbolAddress((void**)&hA,   g_hA);
    cudaGetSymbolAddress((void**)&hB,   g_hB);
    cudaGetSymbolAddress((void**)&bsum, g_bsum);
    cudaGetSymbolAddress((void**)&h0,   g_h0);
    cudaGetSymbolAddress((void**)&h1,   g_h1);
    cudaGetSymbolAddress((void**)&Ah,   g_Ah);
    cudaGetSymbolAddress((void**)&Al,   g_Al);
    cudaGetSymbolAddress((void**)&Bh,   g_Bh);
    cudaGetSymbolAddress((void**)&Bl,   g_Bl);

    cudaFuncSetAttribute(lstm_persist, cudaFuncAttributeMaxDynamicSharedMemorySize, 65536);
    cudaFuncSetAttribute(gemm_mma,    cudaFuncAttributeMaxDynamicSharedMemorySize, 4 * GS_STAGE);

    const int B = 16, H = 1024;
    const int GSM = 4 * GS_STAGE;

    // ---- SRU layer 0: (B,1024,128) -> (1024,B,1024) ----
    ln_rows<<<16384, 256>>>(x, xn, Ah, Al, g0, be0, 1024, B, 128, 1, 0);
    { dim3 g(4096 / 32, 128 / 32); dim3 bl(32, 8);
      transpose_split<<<g, bl>>>(w0, Bh, Bl, 128, 4096); }
    { dim3 g(32, 128); gemm_mma<<<g, 256, GSM>>>(Ah, Al, Bh, Bl, nullptr, U, 128, 4096, 4096); }
    sru_scan<<<256, 64>>>(U, nullptr, vc0, b0, hA, 1024, B, H, 4);

    float* cur = hA; float* alt = hB;

    // ---- SRU layers 1-3 (L=1024) ----
    for (int i = 0; i < 3; i++) {
        ln_rows<<<16384, 256>>>(cur, xn, Ah, Al, Gs + i * H, Bes + i * H, 1024, B, H, 0, 0);
        { dim3 g(3072 / 32, 1024 / 32); dim3 bl(32, 8);
          transpose_split<<<g, bl>>>(Ws + (size_t)i * H * 3072, Bh, Bl, 1024, 3072); }
        { dim3 g(24, 128); gemm_mma<<<g, 256, GSM>>>(Ah, Al, Bh, Bl, nullptr, U, 1024, 3072, 3072); }
        sru_scan<<<256, 64>>>(U, xn, VCs + i * 2048, Bsb + i * 2048, alt, 1024, B, H, 3);
        float* t2 = cur; cur = alt; alt = t2;
    }

    // ---- time pooling 1024 -> 512 ----
    pool2<<<32768, 256>>>(cur, alt, 512 * 16 * 1024);
    { float* t2 = cur; cur = alt; alt = t2; }

    // ---- SRU layers 4-6 (L=512) ----
    for (int i = 3; i < 6; i++) {
        ln_rows<<<8192, 256>>>(cur, xn, Ah, Al, Gs + i * H, Bes + i * H, 512, B, H, 0, 0);
        { dim3 g(3072 / 32, 1024 / 32); dim3 bl(32, 8);
          transpose_split<<<g, bl>>>(Ws + (size_t)i * H * 3072, Bh, Bl, 1024, 3072); }
        { dim3 g(24, 64); gemm_mma<<<g, 256, GSM>>>(Ah, Al, Bh, Bl, nullptr, U, 1024, 3072, 3072); }
        sru_scan<<<256, 64>>>(U, xn, VCs + i * 2048, Bsb + i * 2048, alt, 512, B, H, 3);
        float* t2 = cur; cur = alt; alt = t2;
    }

    // ---- LSTM: pre-GEMM (Wih already [4096,1024] = B layout) ----
    addvec<<<16, 256>>>(bih, bhh, bsum, 4096);
    conv_split<<<32768, 256>>>(cur, Ah, Al, 8192 * 1024);
    conv_split<<<16384, 256>>>(Wih, Bh, Bl, 4096 * 1024);
    { dim3 g(32, 64); gemm_mma<<<g, 256, GSM>>>(Ah, Al, Bh, Bl, bsum, U, 1024, 4096, 4096); }
    lstm_init<<<64, 256>>>(h0);
    lstm_persist<<<148, 256, 65536>>>(U, Whh, h0, h1, alt);

    // ---- final LN (written (b,l)-major) + projection to (16,512,1001) ----
    ln_rows<<<8192, 256>>>(alt, xn, Ah, Al, gh, bhv, 512, B, H, 0, 1);
    { dim3 g(1024 / 32, 1024 / 32); dim3 bl(32, 8);
      transpose_split<<<g, bl>>>(Wout, Bh, Bl, 1024, 1001); }
    { dim3 g(8, 64); gemm_mma<<<g, 256, GSM>>>(Ah, Al, Bh, Bl, nullptr, out, 1024, 1001, 1001); }
}

// round 11
// speedup vs baseline: 2.0484x; 1.0323x over previous
#include <cuda_runtime.h>
#include <cuda_bf16.h>
#include <cstdint>
#include <cstddef>

// ---------------------------------------------------------------------------
// Scratch (device globals; no allocation allowed anywhere)
// ---------------------------------------------------------------------------
__device__ float g_xn [16777216];   // max 16384 rows x 1024
__device__ float g_U  [67108864];   // 1024*16*4096
__device__ float g_hA [16777216];
__device__ float g_hB [16777216];
__device__ float g_bsum[4096];
__device__ float g_h0 [16384];
__device__ unsigned g_bar_count;
__device__ __nv_bfloat16 g_Ah[16777216];  // activation hi split
__device__ __nv_bfloat16 g_Al[16777216];  // activation lo split
__device__ __nv_bfloat16 g_Bh[4194304];   // weight hi split [Npad][K]
__device__ __nv_bfloat16 g_Bl[4194304];   // weight lo split

#define LN_EPS 1e-5f

__device__ __forceinline__ float sigf(float x) {
    return __fdividef(1.f, 1.f + __expf(-x));
}

__device__ __forceinline__ uint32_t smem_to_u32(const void* p) {
    uint32_t a;
    asm("{ .reg .u64 t; cvta.to.shared.u64 t, %1; cvt.u32.u64 %0, t; }"
        : "=r"(a) : "l"(p));
    return a;
}

// packed f32x2 fma: acc(lo,hi) += a(lo,hi) * b(lo,hi)
__device__ __forceinline__ void fma_f32x2(unsigned long long& acc,
                                          unsigned long long a,
                                          unsigned long long b) {
    asm("fma.rn.f32x2 %0, %1, %2, %0;" : "+l"(acc) : "l"(a), "l"(b));
}
union F2U { unsigned long long u; float2 f; };

// ---------------------------------------------------------------------------
// mma.sync / ldmatrix / cp.async primitives (base sm_103 target)
// ---------------------------------------------------------------------------
__device__ __forceinline__ void ldm_x4(uint32_t* r, uint32_t addr) {
    asm volatile("ldmatrix.sync.aligned.m8n8.x4.shared.b16 {%0,%1,%2,%3}, [%4];"
                 : "=r"(r[0]), "=r"(r[1]), "=r"(r[2]), "=r"(r[3]) : "r"(addr));
}
__device__ __forceinline__ void mma_bf16(float* d, const uint32_t* a,
                                         uint32_t b0, uint32_t b1) {
    asm volatile(
        "mma.sync.aligned.m16n8k16.row.col.f32.bf16.bf16.f32 "
        "{%0,%1,%2,%3}, {%4,%5,%6,%7}, {%8,%9}, {%0,%1,%2,%3};"
        : "+f"(d[0]), "+f"(d[1]), "+f"(d[2]), "+f"(d[3])
        : "r"(a[0]), "r"(a[1]), "r"(a[2]), "r"(a[3]), "r"(b0), "r"(b1));
}
__device__ __forceinline__ void cp_async16(uint32_t saddr, const void* gptr) {
    asm volatile("cp.async.cg.shared.global [%0], [%1], 16;"
                 :: "r"(saddr), "l"(__cvta_generic_to_global(gptr)));
}
#define CP_COMMIT()  asm volatile("cp.async.commit_group;" ::: "memory")
#define CP_WAIT(n)   asm volatile("cp.async.wait_group %0;" :: "n"(n) : "memory")

// ---------------------------------------------------------------------------
// Block reduction helper (256-thread blocks)
// ---------------------------------------------------------------------------
__device__ __forceinline__ float blockReduceSum(float v, float* shm) {
    int lane = threadIdx.x & 31, wid = threadIdx.x >> 5;
    #pragma unroll
    for (int o = 16; o; o >>= 1) v += __shfl_xor_sync(0xffffffffu, v, o);
    if (lane == 0) shm[wid] = v;
    __syncthreads();
    int nw = (blockDim.x + 31) >> 5;
    float r = (threadIdx.x < nw) ? shm[threadIdx.x] : 0.f;
    if (wid == 0) {
        #pragma unroll
        for (int o = 16; o; o >>= 1) r += __shfl_xor_sync(0xffffffffu, r, o);
        if (lane == 0) shm[0] = r;
    }
    __syncthreads();
    float total = shm[0];
    __syncthreads();
    return total;
}

// ---------------------------------------------------------------------------
// LayerNorm over last dim, fused bf16 hi/lo split output (hi/lo nullable).
// ---------------------------------------------------------------------------
__global__ __launch_bounds__(256) void ln_rows(
    const float* __restrict__ src, float* __restrict__ dst,
    __nv_bfloat16* __restrict__ hi, __nv_bfloat16* __restrict__ lo,
    const float* __restrict__ g, const float* __restrict__ be,
    int L, int Bb, int D, int srcBMajor, int dstBMajor)
{
    __shared__ float shm[32];
    int r = blockIdx.x;
    int l = r / Bb, b = r % Bb;
    const float* s = src + (srcBMajor ? ((size_t)b * L + l) : (size_t)r) * D;
    size_t drow = (dstBMajor ? ((size_t)b * L + l) : (size_t)r) * D;
    float* d = dst + drow;

    float sum = 0.f;
    for (int i = 4 * threadIdx.x; i < D; i += 1024) {
        float4 v = *(const float4*)(s + i);
        sum += (v.x + v.y) + (v.z + v.w);
    }
    float mean = blockReduceSum(sum, shm) / (float)D;

    float vs = 0.f;
    for (int i = 4 * threadIdx.x; i < D; i += 1024) {
        float4 v = *(const float4*)(s + i);
        float a = v.x - mean, bq = v.y - mean, c = v.z - mean, e = v.w - mean;
        vs += a * a + bq * bq + c * c + e * e;
    }
    float var = blockReduceSum(vs, shm) / (float)D;
    float rstd = rsqrtf(var + LN_EPS);

    for (int i = 4 * threadIdx.x; i < D; i += 1024) {
        float4 v = *(const float4*)(s + i);
        float4 gv = *(const float4*)(g + i);
        float4 bv = *(const float4*)(be + i);
        float4 o;
        o.x = (v.x - mean) * rstd * gv.x + bv.x;
        o.y = (v.y - mean) * rstd * gv.y + bv.y;
        o.z = (v.z - mean) * rstd * gv.z + bv.z;
        o.w = (v.w - mean) * rstd * gv.w + bv.w;
        *(float4*)(d + i) = o;
        if (hi) {
            __nv_bfloat16 h0v = __float2bfloat16(o.x);
            __nv_bfloat16 h1v = __float2bfloat16(o.y);
            __nv_bfloat16 h2v = __float2bfloat16(o.z);
            __nv_bfloat16 h3v = __float2bfloat16(o.w);
            __nv_bfloat162* hp = (__nv_bfloat162*)(hi + drow + i);
            __nv_bfloat162* lp = (__nv_bfloat162*)(lo + drow + i);
            hp[0] = __nv_bfloat162(h0v, h1v);
            hp[1] = __nv_bfloat162(h2v, h3v);
            lp[0] = __nv_bfloat162(
                __float2bfloat16(o.x - __bfloat162float(h0v)),
                __float2bfloat16(o.y - __bfloat162float(h1v)));
            lp[1] = __nv_bfloat162(
                __float2bfloat16(o.z - __bfloat162float(h2v)),
                __float2bfloat16(o.w - __bfloat162float(h3v)));
        }
    }
}

// ---------------------------------------------------------------------------
// Split conversion: fp32 -> (bf16 hi, bf16 lo)
// ---------------------------------------------------------------------------
__global__ void conv_split(const float* __restrict__ x,
                           __nv_bfloat16* __restrict__ hi,
                           __nv_bfloat16* __restrict__ lo, int n)
{
    int i = blockIdx.x * blockDim.x + threadIdx.x;
    if (i >= n) return;
    float v = x[i];
    __nv_bfloat16 h = __float2bfloat16(v);
    hi[i] = h;
    lo[i] = __float2bfloat16(v - __bfloat162float(h));
}

// W[K][N] -> Bh/Bl [Npad][K] (zero rows for n >= N). grid (Npad/32, K/32), block (32,8)
__global__ void transpose_split(const float* __restrict__ W,
                                __nv_bfloat16* __restrict__ Bh,
                                __nv_bfloat16* __restrict__ Bl,
                                int K, int N)
{
    __shared__ float t[32][33];
    int n0 = blockIdx.x * 32, k0 = blockIdx.y * 32;
    int x = threadIdx.x, y = threadIdx.y;
    #pragma unroll
    for (int j = 0; j < 32; j += 8) {
        int k = k0 + y + j, n = n0 + x;
        t[y + j][x] = (n < N) ? W[(size_t)k * N + n] : 0.f;
    }
    __syncthreads();
    #pragma unroll
    for (int j = 0; j < 32; j += 8) {
        int n = n0 + y + j, k = k0 + x;
        float v = t[x][y + j];
        __nv_bfloat16 h = __float2bfloat16(v);
        Bh[(size_t)n * K + k] = h;
        Bl[(size_t)n * K + k] = __float2bfloat16(v - __bfloat162float(h));
    }
}

// ---------------------------------------------------------------------------
// Split-bf16 GEMM via mma.sync (4-stage ring, BK=16). Epilogue: float2
// stores ONLY when ldC is even (odd ldC breaks 8B alignment -> trap).
// ---------------------------------------------------------------------------
#define GS_A_LO  6144
#define GS_B_HI  12288
#define GS_B_LO  18432
#define GS_STAGE 24576

__global__ __launch_bounds__(256) void gemm_mma(
    const __nv_bfloat16* __restrict__ Ah, const __nv_bfloat16* __restrict__ Al,
    const __nv_bfloat16* __restrict__ Bh, const __nv_bfloat16* __restrict__ Bl,
    const float* __restrict__ bias, float* __restrict__ C,
    int K, int Nreal, int ldC)
{
    extern __shared__ char smem[];
    const uint32_t sb = smem_to_u32(smem);
    const int tid = threadIdx.x, warp = tid >> 5, lane = tid & 31;
    const int n0 = blockIdx.x * 128, m0 = blockIdx.y * 128;
    const int warpM = warp >> 2, warpN = warp & 3;      // 2 x 4
    const int S = K >> 4;                                // BK = 16

    float d[4][4][4];
    #pragma unroll
    for (int mt = 0; mt < 4; mt++)
        #pragma unroll
        for (int nt = 0; nt < 4; nt++)
            #pragma unroll
            for (int e = 0; e < 4; e++) d[mt][nt][e] = 0.f;

    const int lrow = tid >> 1, lc = tid & 1;
    auto load_stage = [&](int s, int buf) {
        const size_t kc = ((size_t)s << 4) + lc * 8;
        uint32_t so = (uint32_t)buf * GS_STAGE + lrow * 48 + lc * 16;
        size_t ga = (size_t)(m0 + lrow) * K + kc;
        size_t gb = (size_t)(n0 + lrow) * K + kc;
        cp_async16(sb + so,           Ah + ga);
        cp_async16(sb + so + GS_A_LO, Al + ga);
        cp_async16(sb + so + GS_B_HI, Bh + gb);
        cp_async16(sb + so + GS_B_LO, Bl + gb);
        CP_COMMIT();
    };

    load_stage(0, 0);
    load_stage(1, 1);
    load_stage(2, 2);

    const uint32_t off = (uint32_t)(lane & 15) * 48 + (uint32_t)(lane >> 4) * 16;

    for (int s = 0; s < S; s++) {
        if (s <= S - 3)      CP_WAIT(2);
        else if (s == S - 2) CP_WAIT(1);
        else                 CP_WAIT(0);
        __syncthreads();
        if (s + 3 < S) load_stage(s + 3, (s + 3) & 3);

        const uint32_t base  = sb + (uint32_t)(s & 3) * GS_STAGE;
        const uint32_t aBase = base + (uint32_t)(warpM * 64) * 48;
        const uint32_t bBase = base + GS_B_HI + (uint32_t)(warpN * 32) * 48;

        uint32_t aH[4][4], aL[4][4], bH[2][4], bL[2][4];
        #pragma unroll
        for (int mt = 0; mt < 4; mt++) {
            uint32_t ad = aBase + (uint32_t)(mt * 16) * 48 + off;
            ldm_x4(aH[mt], ad);
            ldm_x4(aL[mt], ad + GS_A_LO);
        }
        #pragma unroll
        for (int ng = 0; ng < 2; ng++) {
            uint32_t bd = bBase + (uint32_t)(ng * 16) * 48 + off;
            ldm_x4(bH[ng], bd);
            ldm_x4(bL[ng], bd + (GS_B_LO - GS_B_HI));
        }
        #pragma unroll
        for (int mt = 0; mt < 4; mt++)
            #pragma unroll
            for (int ng = 0; ng < 2; ng++) {
                mma_bf16(d[mt][2 * ng],     aH[mt], bH[ng][0], bH[ng][2]);
                mma_bf16(d[mt][2 * ng + 1], aH[mt], bH[ng][1], bH[ng][3]);
                mma_bf16(d[mt][2 * ng],     aH[mt], bL[ng][0], bL[ng][2]);
                mma_bf16(d[mt][2 * ng + 1], aH[mt], bL[ng][1], bL[ng][3]);
                mma_bf16(d[mt][2 * ng],     aL[mt], bH[ng][0], bH[ng][2]);
                mma_bf16(d[mt][2 * ng + 1], aL[mt], bH[ng][1], bH[ng][3]);
            }
    }

    const int r0 = m0 + warpM * 64 + (lane >> 2);
    const int c0 = n0 + warpN * 32 + (lane & 3) * 2;
    const bool vec = ((ldC & 1) == 0);
    #pragma unroll
    for (int mt = 0; mt < 4; mt++) {
        #pragma unroll
        for (int nt = 0; nt < 4; nt++) {
            int cc = c0 + nt * 8;
            float* p0 = C + (size_t)(r0 + mt * 16) * ldC;
            float* p1 = p0 + 8 * (size_t)ldC;
            if (vec && cc + 1 < Nreal) {
                float b0v = bias ? bias[cc] : 0.f;
                float b1v = bias ? bias[cc + 1] : 0.f;
                *(float2*)(p0 + cc) = make_float2(d[mt][nt][0] + b0v, d[mt][nt][1] + b1v);
                *(float2*)(p1 + cc) = make_float2(d[mt][nt][2] + b0v, d[mt][nt][3] + b1v);
            } else {
                if (cc < Nreal) {
                    float bv = bias ? bias[cc] : 0.f;
                    p0[cc] = d[mt][nt][0] + bv;
                    p1[cc] = d[mt][nt][2] + bv;
                }
                if (cc + 1 < Nreal) {
                    float bv = bias ? bias[cc + 1] : 0.f;
                    p0[cc + 1] = d[mt][nt][1] + bv;
                    p1[cc + 1] = d[mt][nt][3] + bv;
                }
            }
        }
    }
}

// ---------------------------------------------------------------------------
// SRU scan: 16384 recurrences; 16-deep register prefetch ring. Biases are
// folded (negated) into the prefetched a1/a2 so the serial c-chain is
// FFMA -> EX2 -> FADD -> RCP only.
// ---------------------------------------------------------------------------
__global__ void sru_scan(
    const float* __restrict__ U, const float* __restrict__ res,
    const float* __restrict__ vc, const float* __restrict__ bias,
    float* __restrict__ out, int L, int Bb, int H, int k)
{
    int idx = blockIdx.x * blockDim.x + threadIdx.x;
    if (idx >= Bb * H) return;
    int hh = idx % H, b = idx / H;
    float vfn = -vc[hh], vrn = -vc[H + hh];
    float bf = bias[hh], br = bias[H + hh];
    float c = 0.f;

    size_t ustep = (size_t)Bb * k * H;
    size_t ubase = (size_t)b * k * H + hh;
    size_t ostep = (size_t)Bb * H;
    size_t obase = (size_t)b * H + hh;

    const float* u  = U + ubase;
    const float* rp = (k == 3) ? (res + obase) : (U + ubase + 3 * (size_t)H);
    size_t rstep    = (k == 3) ? ostep : ustep;
    float* o = out + obase;

    float pa0[16], pa1[16], pa2[16], prt[16];
    #pragma unroll
    for (int j = 0; j < 16; j++) {
        size_t uo = (size_t)j * ustep;
        pa0[j] = __ldcs(u + uo);
        pa1[j] = -(__ldcs(u + uo + H) + bf);
        pa2[j] = -(__ldcs(u + uo + 2 * (size_t)H) + br);
        prt[j] = __ldcs(rp + (size_t)j * rstep);
    }

    #pragma unroll 16
    for (int t = 0; t < L; ++t) {
        int j = t & 15;
        float a0 = pa0[j], a1n = pa1[j], a2n = pa2[j], rt = prt[j];
        int tn = (t + 16 < L) ? (t + 16) : (L - 1);
        size_t uo = (size_t)tn * ustep;
        pa0[j] = __ldcs(u + uo);
        pa1[j] = -(__ldcs(u + uo + H) + bf);
        pa2[j] = -(__ldcs(u + uo + 2 * (size_t)H) + br);
        prt[j] = __ldcs(rp + (size_t)tn * rstep);

        // f = sigmoid(a1 + vf*c + bf) = 1/(1 + exp(a1n + vfn*c))
        float e1 = __expf(fmaf(vfn, c, a1n));
        float f  = __fdividef(1.f, 1.f + e1);
        float e2 = __expf(fmaf(vrn, c, a2n));
        float r  = __fdividef(1.f, 1.f + e2);
        c = fmaf(f, c - a0, a0);
        o[(size_t)t * ostep] = fmaf(r, c - rt, rt);
    }
}

__global__ void pool2(const float* __restrict__ in, float* __restrict__ out, int n)
{
    int i = blockIdx.x * blockDim.x + threadIdx.x;
    if (i >= n) return;
    int lp = i >> 14;
    size_t j = (size_t)i + (size_t)lp * 16384;
    out[i] = 0.5f * (in[j] + in[j + 16384]);
}

__global__ void addvec(const float* __restrict__ a, const float* __restrict__ b,
                       float* __restrict__ o, int n)
{
    int i = blockIdx.x * blockDim.x + threadIdx.x;
    if (i < n) o[i] = a[i] + b[i];
}

__global__ void lstm_init(float* h0)
{
    int i = blockIdx.x * blockDim.x + threadIdx.x;
    if (i < 16384) h0[i] = 0.f;
    if (i == 0) g_bar_count = 0u;
}

// ---------------------------------------------------------------------------
// Persistent LSTM (148 CTAs). f32x2 packed fma; h staged via cp.async in two
// K-halves. Grid barrier: monotonic counter via red.global (no-return, no
// L2 round trip) + L2 poll -- much cheaper than atomicAdd-with-return.
// h(t-1) is read straight from hout (no ping-pong buffers).
// ---------------------------------------------------------------------------
__global__ __launch_bounds__(256) void lstm_persist(
    const float* __restrict__ pre, const float* __restrict__ Whh,
    const float* __restrict__ h0, float* __restrict__ hout)
{
    extern __shared__ float hs[];    // 16 x 1024 floats = 64 KB
    const ulonglong2* hs2 = (const ulonglong2*)hs;
    const uint32_t hs_sb = smem_to_u32(hs);
    const int tid = threadIdx.x, bid = blockIdx.x;
    const int warp = tid >> 5, lane = tid & 31;

    int cnt, s;
    if (bid < 136) { cnt = 7; s = bid * 7; }
    else           { cnt = 6; s = 952 + (bid - 136) * 6; }
    const bool active = warp < cnt;
    const int hh = s + (active ? warp : 0);

    const ulonglong2* W2[4];
    #pragma unroll
    for (int g = 0; g < 4; g++)
        W2[g] = (const ulonglong2*)(Whh + ((size_t)g * 1024 + hh) * 1024);

    unsigned* barp;
    { unsigned* t; asm("cvta.global.u64 %0, %1;" : "=l"(t) : "l"(&g_bar_count)); barp = t; }

    float c = 0.f;

    for (int t = 0; t < 512; t++) {
        const float* hsrc = (t == 0) ? h0 : (hout + (size_t)(t - 1) * 16384);

        __syncthreads();   // everyone past barrier; hs reusable

        // stage h: two 32 KB halves (split along K) via cp.async.cg
        #pragma unroll
        for (int half = 0; half < 2; half++) {
            #pragma unroll
            for (int j2 = 0; j2 < 8; j2++) {
                int cidx = tid + j2 * 256;           // 0..2047
                int b = cidx >> 7, kc = cidx & 127;
                uint32_t foff = (uint32_t)(b * 1024 + half * 512 + kc * 4);
                cp_async16(hs_sb + foff * 4, hsrc + foff);
            }
            CP_COMMIT();
        }

        // prefetch pre gate values (independent of h)
        float pv0 = 0.f, pv1 = 0.f, pv2 = 0.f, pv3 = 0.f;
        if (active && lane < 16) {
            const float* pb = pre + (size_t)t * 65536 + (size_t)lane * 4096;
            pv0 = __ldcg(pb + hh);
            pv1 = __ldcg(pb + 1024 + hh);
            pv2 = __ldcg(pb + 2048 + hh);
            pv3 = __ldcg(pb + 3072 + hh);
        }

        unsigned long long acc2[4][16];
        #pragma unroll
        for (int g = 0; g < 4; g++)
            #pragma unroll
            for (int b = 0; b < 16; b++) acc2[g][b] = 0ull;

        CP_WAIT(1);
        __syncthreads();     // half 1 (K 0..511) resident
        if (active) {
            #pragma unroll 1
            for (int i = lane; i < 128; i += 32) {
                ulonglong2 wq[4];
                #pragma unroll
                for (int g = 0; g < 4; g++) wq[g] = W2[g][i];
                #pragma unroll
                for (int b = 0; b < 16; b++) {
                    ulonglong2 hq = hs2[b * 256 + i];
                    #pragma unroll
                    for (int g = 0; g < 4; g++) {
                        fma_f32x2(acc2[g][b], wq[g].x, hq.x);
                        fma_f32x2(acc2[g][b], wq[g].y, hq.y);
                    }
                }
            }
        }
        CP_WAIT(0);
        __syncthreads();     // half 2 resident
        if (active) {
            #pragma unroll 1
            for (int i = 128 + lane; i < 256; i += 32) {
                ulonglong2 wq[4];
                #pragma unroll
                for (int g = 0; g < 4; g++) wq[g] = W2[g][i];
                #pragma unroll
                for (int b = 0; b < 16; b++) {
                    ulonglong2 hq = hs2[b * 256 + i];
                    #pragma unroll
                    for (int g = 0; g < 4; g++) {
                        fma_f32x2(acc2[g][b], wq[g].x, hq.x);
                        fma_f32x2(acc2[g][b], wq[g].y, hq.y);
                    }
                }
            }

            float gate[4] = {0.f, 0.f, 0.f, 0.f};
            #pragma unroll
            for (int g = 0; g < 4; g++)
                #pragma unroll
                for (int b = 0; b < 16; b++) {
                    F2U u2; u2.u = acc2[g][b];
                    float v = u2.f.x + u2.f.y;
                    #pragma unroll
                    for (int o = 16; o; o >>= 1)
                        v += __shfl_xor_sync(0xffffffffu, v, o);
                    if (lane == b) gate[g] = v;
                }

            if (lane < 16) {
                float ig = sigf(gate[0] + pv0);
                float fg = sigf(gate[1] + pv1);
                float gg = tanhf(gate[2] + pv2);
                float og = sigf(gate[3] + pv3);
                c = fg * c + ig * gg;
                float hv = og * tanhf(c);
                hout[(size_t)t * 16384 + lane * 1024 + hh] = hv;
            }
        }

        // ---- grid barrier: monotonic red.global counter, L2 poll ----
        __syncthreads();
        if (tid == 0) {
            __threadfence();
            asm volatile("red.global.add.u32 [%0], %1;" :: "l"(barp), "r"(1u) : "memory");
            unsigned target = 148u * (unsigned)(t + 1);
            unsigned v;
            do {
                asm volatile("ld.global.cg.u32 %0, [%1];" : "=r"(v) : "l"(barp) : "memory");
                if (v >= target) break;
                __nanosleep(32);
            } while (true);
            __threadfence();
        }
        // loop-top __syncthreads releases the block
    }
}

// ---------------------------------------------------------------------------
// Orchestration
// ---------------------------------------------------------------------------
extern "C" void kernel_launch(void* const* d_in, const int* in_sizes, int n_in,
                              void* d_out, int out_size)
{
    const float* x    = (const float*)d_in[0];
    const float* w0   = (const float*)d_in[1];
    const float* vc0  = (const float*)d_in[2];
    const float* b0   = (const float*)d_in[3];
    const float* g0   = (const float*)d_in[4];
    const float* be0  = (const float*)d_in[5];
    const float* Ws   = (const float*)d_in[6];
    const float* VCs  = (const float*)d_in[7];
    const float* Bsb  = (const float*)d_in[8];
    const float* Gs   = (const float*)d_in[9];
    const float* Bes  = (const float*)d_in[10];
    const float* Wih  = (const float*)d_in[11];
    const float* Whh  = (const float*)d_in[12];
    const float* bih  = (const float*)d_in[13];
    const float* bhh  = (const float*)d_in[14];
    const float* gh   = (const float*)d_in[15];
    const float* bhv  = (const float*)d_in[16];
    const float* Wout = (const float*)d_in[17];
    float* out = (float*)d_out;

    float *xn, *U, *hA, *hB, *bsum, *h0;
    __nv_bfloat16 *Ah, *Al, *Bh, *Bl;
    cudaGetSymbolAddress((void**)&xn,   g_xn);
    cudaGetSymbolAddress((void**)&U,    g_U);
    cudaGetSymbolAddress((void**)&hA,   g_hA);
    cudaGetSymbolAddress((void**)&hB,   g_hB);
    cudaGetSymbolAddress((void**)&bsum, g_bsum);
    cudaGetSymbolAddress((void**)&h0,   g_h0);
    cudaGetSymbolAddress((void**)&Ah,   g_Ah);
    cudaGetSymbolAddress((void**)&Al,   g_Al);
    cudaGetSymbolAddress((void**)&Bh,   g_Bh);
    cudaGetSymbolAddress((void**)&Bl,   g_Bl);

    cudaFuncSetAttribute(lstm_persist, cudaFuncAttributeMaxDynamicSharedMemorySize, 65536);
    cudaFuncSetAttribute(gemm_mma,    cudaFuncAttributeMaxDynamicSharedMemorySize, 4 * GS_STAGE);

    const int B = 16, H = 1024;
    const int GSM = 4 * GS_STAGE;

    // ---- SRU layer 0: (B,1024,128) -> (1024,B,1024) ----
    ln_rows<<<16384, 256>>>(x, xn, Ah, Al, g0, be0, 1024, B, 128, 1, 0);
    { dim3 g(4096 / 32, 128 / 32); dim3 bl(32, 8);
      transpose_split<<<g, bl>>>(w0, Bh, Bl, 128, 4096); }
    { dim3 g(32, 128); gemm_mma<<<g, 256, GSM>>>(Ah, Al, Bh, Bl, nullptr, U, 128, 4096, 4096); }
    sru_scan<<<256, 64>>>(U, nullptr, vc0, b0, hA, 1024, B, H, 4);

    float* cur = hA; float* alt = hB;

    // ---- SRU layers 1-3 (L=1024) ----
    for (int i = 0; i < 3; i++) {
        ln_rows<<<16384, 256>>>(cur, xn, Ah, Al, Gs + i * H, Bes + i * H, 1024, B, H, 0, 0);
        { dim3 g(3072 / 32, 1024 / 32); dim3 bl(32, 8);
          transpose_split<<<g, bl>>>(Ws + (size_t)i * H * 3072, Bh, Bl, 1024, 3072); }
        { dim3 g(24, 128); gemm_mma<<<g, 256, GSM>>>(Ah, Al, Bh, Bl, nullptr, U, 1024, 3072, 3072); }
        sru_scan<<<256, 64>>>(U, xn, VCs + i * 2048, Bsb + i * 2048, alt, 1024, B, H, 3);
        float* t2 = cur; cur = alt; alt = t2;
    }

    // ---- time pooling 1024 -> 512 ----
    pool2<<<32768, 256>>>(cur, alt, 512 * 16 * 1024);
    { float* t2 = cur; cur = alt; alt = t2; }

    // ---- SRU layers 4-6 (L=512) ----
    for (int i = 3; i < 6; i++) {
        ln_rows<<<8192, 256>>>(cur, xn, Ah, Al, Gs + i * H, Bes + i * H, 512, B, H, 0, 0);
        { dim3 g(3072 / 32, 1024 / 32); dim3 bl(32, 8);
          transpose_split<<<g, bl>>>(Ws + (size_t)i * H * 3072, Bh, Bl, 1024, 3072); }
        { dim3 g(24, 64); gemm_mma<<<g, 256, GSM>>>(Ah, Al, Bh, Bl, nullptr, U, 1024, 3072, 3072); }
        sru_scan<<<256, 64>>>(U, xn, VCs + i * 2048, Bsb + i * 2048, alt, 512, B, H, 3);
        float* t2 = cur; cur = alt; alt = t2;
    }

    // ---- LSTM: pre-GEMM (Wih already [4096,1024] = B layout) ----
    addvec<<<16, 256>>>(bih, bhh, bsum, 4096);
    conv_split<<<32768, 256>>>(cur, Ah, Al, 8192 * 1024);
    conv_split<<<16384, 256>>>(Wih, Bh, Bl, 4096 * 1024);
    { dim3 g(32, 64); gemm_mma<<<g, 256, GSM>>>(Ah, Al, Bh, Bl, bsum, U, 1024, 4096, 4096); }
    lstm_init<<<64, 256>>>(h0);
    lstm_persist<<<148, 256, 65536>>>(U, Whh, h0, alt);

    // ---- final LN (written (b,l)-major) + projection to (16,512,1001) ----
    ln_rows<<<8192, 256>>>(alt, xn, Ah, Al, gh, bhv, 512, B, H, 0, 1);
    { dim3 g(1024 / 32, 1024 / 32); dim3 bl(32, 8);
      transpose_split<<<g, bl>>>(Wout, Bh, Bl, 1024, 1001); }
    { dim3 g(8, 64); gemm_mma<<<g, 256, GSM>>>(Ah, Al, Bh, Bl, nullptr, out, 1024, 1001, 1001); }
}